// round 2
// baseline (speedup 1.0000x reference)
#include <cuda_runtime.h>
#include <math.h>

#define N_NODES 50000
#define N_EDGES 800000
#define N_GRAPHS 256
#define D_IN 14
#define D_HID 256

// ---- persistent device scratch (no dynamic allocation allowed) ----
__device__ float g_bufA[N_NODES * D_HID];   // 51.2 MB
__device__ float g_bufB[N_NODES * D_HID];   // 51.2 MB
__device__ float g_dinv[N_NODES];
__device__ int   g_deg[N_NODES];
__device__ int   g_rowptr[N_NODES + 1];
__device__ int   g_cursor[N_NODES];
__device__ int   g_col[N_EDGES];
__device__ int   g_gcnt[N_GRAPHS];
__device__ int   g_gptr[N_GRAPHS + 1];
__device__ float g_pool[N_GRAPHS * D_HID];
__device__ float g_fc1o[N_GRAPHS * 128];

__device__ __forceinline__ float selu_f(float x) {
    const float scale = 1.0507009873554805f;
    const float alpha = 1.6732632423543772f;
    return x > 0.f ? scale * x : scale * alpha * (expf(x) - 1.f);
}

// ---- CSR build ----
__global__ void k_zero() {
    int i = blockIdx.x * blockDim.x + threadIdx.x;
    if (i < N_NODES) g_deg[i] = 0;
    if (i < N_GRAPHS) g_gcnt[i] = 0;
}

__global__ void k_hist_edges(const int* __restrict__ ei) {
    int e = blockIdx.x * blockDim.x + threadIdx.x;
    if (e < N_EDGES) {
        int d = ei[N_EDGES + e];
        atomicAdd(&g_deg[d], 1);
    }
}

__global__ void k_hist_batch(const int* __restrict__ b) {
    int i = blockIdx.x * blockDim.x + threadIdx.x;
    if (i < N_NODES) atomicAdd(&g_gcnt[b[i]], 1);
}

// single-block exclusive scan over 50000 degrees + 256 graph counts
__global__ void k_scan() {
    __shared__ int wsum[32];
    __shared__ int s_carry;
    int tid = threadIdx.x, lane = tid & 31, wid = tid >> 5;
    if (tid == 0) s_carry = 0;
    __syncthreads();
    for (int base = 0; base < N_NODES; base += 1024) {
        int i = base + tid;
        int v = (i < N_NODES) ? g_deg[i] : 0;
        int xv = v;
        #pragma unroll
        for (int o = 1; o < 32; o <<= 1) {
            int t = __shfl_up_sync(0xffffffffu, xv, o);
            if (lane >= o) xv += t;
        }
        if (lane == 31) wsum[wid] = xv;
        __syncthreads();
        if (wid == 0) {
            int s = wsum[lane];
            #pragma unroll
            for (int o = 1; o < 32; o <<= 1) {
                int t = __shfl_up_sync(0xffffffffu, s, o);
                if (lane >= o) s += t;
            }
            wsum[lane] = s;
        }
        __syncthreads();
        int offs = (wid > 0) ? wsum[wid - 1] : 0;
        int excl = xv - v + offs + s_carry;
        if (i < N_NODES) { g_rowptr[i] = excl; g_cursor[i] = excl; }
        int tot = wsum[31];
        __syncthreads();
        if (tid == 0) s_carry += tot;
        __syncthreads();
    }
    if (tid == 0) g_rowptr[N_NODES] = s_carry;
    // graph pointer scan (256 entries), warp 0 only
    if (wid == 0) {
        int c[8]; int s = 0; int base = lane * 8;
        #pragma unroll
        for (int k = 0; k < 8; k++) { c[k] = g_gcnt[base + k]; s += c[k]; }
        int incl = s;
        #pragma unroll
        for (int o = 1; o < 32; o <<= 1) {
            int t = __shfl_up_sync(0xffffffffu, incl, o);
            if (lane >= o) incl += t;
        }
        int run = incl - s;
        #pragma unroll
        for (int k = 0; k < 8; k++) { g_gptr[base + k] = run; run += c[k]; }
        if (lane == 31) g_gptr[N_GRAPHS] = run;
    }
}

__global__ void k_dinv() {
    int i = blockIdx.x * blockDim.x + threadIdx.x;
    if (i < N_NODES) g_dinv[i] = rsqrtf((float)(g_deg[i] + 1)); // +1 = self loop
}

__global__ void k_fill(const int* __restrict__ ei) {
    int e = blockIdx.x * blockDim.x + threadIdx.x;
    if (e < N_EDGES) {
        int s = ei[e];
        int d = ei[N_EDGES + e];
        int p = atomicAdd(&g_cursor[d], 1);
        g_col[p] = s;
    }
}

// ---- layer 1 input transform: g_bufA = x @ W1 ----
__global__ void k_in_gemm(const float* __restrict__ x, const float* __restrict__ W1) {
    __shared__ float sW[D_IN * D_HID];   // 14 KB
    __shared__ float sx[16 * D_IN];
    int tid = threadIdx.x;
    for (int i = tid; i < D_IN * D_HID; i += 256) sW[i] = W1[i];
    int n0 = blockIdx.x * 16;
    int cnt = min(16, N_NODES - n0);
    for (int i = tid; i < cnt * D_IN; i += 256) sx[i] = x[(size_t)n0 * D_IN + i];
    __syncthreads();
    for (int r = 0; r < cnt; r++) {
        float acc = 0.f;
        #pragma unroll
        for (int k = 0; k < D_IN; k++) acc += sx[r * D_IN + k] * sW[k * D_HID + tid];
        g_bufA[(size_t)(n0 + r) * D_HID + tid] = acc;
    }
}

// ---- GCN aggregation: g_bufB[n] = selu( sum_msgs + bias ) ; in=g_bufA ----
__global__ void k_aggregate(const float* __restrict__ bias) {
    __shared__ int   sc[128];
    __shared__ float sw[128];
    int n = blockIdx.x, tid = threadIdx.x;
    float dn = g_dinv[n];
    float acc = g_bufA[(size_t)n * D_HID + tid] * dn * dn;  // self loop
    int e0 = g_rowptr[n], e1 = g_rowptr[n + 1];
    for (int base = e0; base < e1; base += 128) {
        int m = min(128, e1 - base);
        if (tid < m) {
            int s = g_col[base + tid];
            sc[tid] = s;
            sw[tid] = g_dinv[s] * dn;
        }
        __syncthreads();
        for (int i = 0; i < m; i++)
            acc += g_bufA[(size_t)sc[i] * D_HID + tid] * sw[i];
        __syncthreads();
    }
    g_bufB[(size_t)n * D_HID + tid] = selu_f(acc + bias[tid]);
}

// ---- g_bufA = g_bufB @ W2 (50000x256 @ 256x256, fp32 SGEMM) ----
__global__ void k_gemm256(const float* __restrict__ B) {
    __shared__ float Ast[16][64];
    __shared__ float Bs[16][64];
    int tid = threadIdx.x;
    int bm = blockIdx.x * 64, bn = blockIdx.y * 64;
    int ty = tid >> 4, tx = tid & 15;
    int lm = tid >> 2, lk4 = tid & 3;
    int lkB = tid >> 4, ln4 = tid & 15;
    float acc[4][4] = {};
    for (int k0 = 0; k0 < 256; k0 += 16) {
        float4 a4 = make_float4(0.f, 0.f, 0.f, 0.f);
        int gm = bm + lm;
        if (gm < N_NODES)
            a4 = *(const float4*)&g_bufB[(size_t)gm * 256 + k0 + lk4 * 4];
        Ast[lk4 * 4 + 0][lm] = a4.x;
        Ast[lk4 * 4 + 1][lm] = a4.y;
        Ast[lk4 * 4 + 2][lm] = a4.z;
        Ast[lk4 * 4 + 3][lm] = a4.w;
        *(float4*)&Bs[lkB][ln4 * 4] = *(const float4*)&B[(size_t)(k0 + lkB) * 256 + bn + ln4 * 4];
        __syncthreads();
        #pragma unroll
        for (int kk = 0; kk < 16; kk++) {
            float4 av = *(float4*)&Ast[kk][ty * 4];
            float4 bv = *(float4*)&Bs[kk][tx * 4];
            float a[4] = {av.x, av.y, av.z, av.w};
            float b[4] = {bv.x, bv.y, bv.z, bv.w};
            #pragma unroll
            for (int i = 0; i < 4; i++)
                #pragma unroll
                for (int j = 0; j < 4; j++)
                    acc[i][j] += a[i] * b[j];
        }
        __syncthreads();
    }
    #pragma unroll
    for (int i = 0; i < 4; i++) {
        int gm = bm + ty * 4 + i;
        if (gm < N_NODES) {
            float4 v = make_float4(acc[i][0], acc[i][1], acc[i][2], acc[i][3]);
            *(float4*)&g_bufA[(size_t)gm * 256 + bn + tx * 4] = v;
        }
    }
}

// ---- global mean pool + selu: reads g_bufB ----
__global__ void k_pool() {
    int g = blockIdx.x, tid = threadIdx.x;
    int s = g_gptr[g], e = g_gptr[g + 1];
    float acc = 0.f;
    for (int n = s; n < e; n++) acc += g_bufB[(size_t)n * D_HID + tid];
    float c = fmaxf((float)(e - s), 1.f);
    g_pool[g * D_HID + tid] = selu_f(acc / c);
}

// ---- fc1 (256->128) + selu ----
__global__ void k_fc1(const float* __restrict__ w, const float* __restrict__ b) {
    __shared__ float sp[D_HID];
    int g = blockIdx.x, tid = threadIdx.x;  // 128 threads
    sp[tid] = g_pool[g * D_HID + tid];
    sp[tid + 128] = g_pool[g * D_HID + tid + 128];
    __syncthreads();
    float acc = b[tid];
    #pragma unroll 8
    for (int k = 0; k < D_HID; k++) acc += sp[k] * w[k * 128 + tid];
    g_fc1o[g * 128 + tid] = selu_f(acc);
}

// ---- fc2 (128->2) + log_softmax ----
__global__ void k_fc2(const float* __restrict__ w, const float* __restrict__ b,
                      float* __restrict__ out) {
    __shared__ float sl[2];
    int g = blockIdx.x, tid = threadIdx.x;  // 64 threads
    int c = tid >> 5, lane = tid & 31;
    float p = 0.f;
    for (int k = lane; k < 128; k += 32) p += g_fc1o[g * 128 + k] * w[k * 2 + c];
    #pragma unroll
    for (int o = 16; o; o >>= 1) p += __shfl_down_sync(0xffffffffu, p, o);
    if (lane == 0) sl[c] = p + b[c];
    __syncthreads();
    if (tid < 2) {
        float l0 = sl[0], l1 = sl[1];
        float m = fmaxf(l0, l1);
        float lse = m + logf(expf(l0 - m) + expf(l1 - m));
        out[g * 2 + tid] = sl[tid] - lse;
    }
}

extern "C" void kernel_launch(void* const* d_in, const int* in_sizes, int n_in,
                              void* d_out, int out_size) {
    const float* x     = (const float*)d_in[0];
    const int*   ei    = (const int*)d_in[1];    // int32: JAX default x64-disabled
    const int*   batch = (const int*)d_in[2];    // int32
    const float* W1    = (const float*)d_in[3];
    const float* b1    = (const float*)d_in[4];
    const float* W2    = (const float*)d_in[5];
    const float* b2    = (const float*)d_in[6];
    const float* fc1w  = (const float*)d_in[7];
    const float* fc1b  = (const float*)d_in[8];
    const float* fc2w  = (const float*)d_in[9];
    const float* fc2b  = (const float*)d_in[10];
    float* out = (float*)d_out;

    // CSR + normalization build (redone every call; deterministic work)
    k_zero<<<(N_NODES + 255) / 256, 256>>>();
    k_hist_edges<<<(N_EDGES + 255) / 256, 256>>>(ei);
    k_hist_batch<<<(N_NODES + 255) / 256, 256>>>(batch);
    k_scan<<<1, 1024>>>();
    k_dinv<<<(N_NODES + 255) / 256, 256>>>();
    k_fill<<<(N_EDGES + 255) / 256, 256>>>(ei);

    // layer 1
    k_in_gemm<<<(N_NODES + 15) / 16, 256>>>(x, W1);
    k_aggregate<<<N_NODES, 256>>>(b1);

    // layer 2
    dim3 g2((N_NODES + 63) / 64, 4);
    k_gemm256<<<g2, 256>>>(W2);
    k_aggregate<<<N_NODES, 256>>>(b2);

    // head
    k_pool<<<N_GRAPHS, 256>>>();
    k_fc1<<<N_GRAPHS, 128>>>(fc1w, fc1b);
    k_fc2<<<N_GRAPHS, 64>>>(fc2w, fc2b, out);
}

// round 3
// speedup vs baseline: 1.5802x; 1.5802x over previous
#include <cuda_runtime.h>
#include <math.h>

#define N_NODES 50000
#define N_EDGES 800000
#define N_GRAPHS 256
#define D_IN 14
#define D_HID 256
#define SCAN_BLOCKS 196   // ceil(50000/256)

// ---- persistent device scratch (no dynamic allocation allowed) ----
__device__ float g_bufA[N_NODES * D_HID];   // 51.2 MB
__device__ float g_bufB[N_NODES * D_HID];   // 51.2 MB
__device__ float g_dinv[N_NODES];
__device__ int   g_deg[N_NODES];
__device__ int   g_rowptr[N_NODES + 1];
__device__ int   g_cursor[N_NODES];
__device__ int   g_col[N_EDGES];
__device__ float g_wt[N_EDGES];
__device__ int   g_bsum[256];
__device__ int   g_boff[256];
__device__ int   g_gptr[N_GRAPHS + 1];

__device__ __forceinline__ float selu_f(float x) {
    const float scale = 1.0507009873554805f;
    const float alpha = 1.6732632423543772f;
    return x > 0.f ? scale * x : scale * alpha * (expf(x) - 1.f);
}

// packed fp32x2 FMA (Blackwell): d = a*b + d per 32-bit half
__device__ __forceinline__ void ffma2(unsigned long long& d,
                                      unsigned long long a,
                                      unsigned long long b) {
    asm("fma.rn.f32x2 %0, %1, %2, %0;" : "+l"(d) : "l"(a), "l"(b));
}
__device__ __forceinline__ unsigned long long dup2(float x) {
    unsigned long long r;
    asm("mov.b64 %0, {%1, %1};" : "=l"(r) : "f"(x));
    return r;
}

// ---- CSR build ----
__global__ void k_zero() {
    int i = blockIdx.x * blockDim.x + threadIdx.x;
    if (i < N_NODES) g_deg[i] = 0;
}

__global__ void k_hist_edges(const int* __restrict__ ei) {
    int e = blockIdx.x * blockDim.x + threadIdx.x;
    if (e < N_EDGES) atomicAdd(&g_deg[ei[N_EDGES + e]], 1);
}

// block-level exclusive scan of degrees; writes partial rowptr, block sums, dinv
__global__ void k_scan1() {
    __shared__ int wsum[8];
    int b = blockIdx.x, t = threadIdx.x, lane = t & 31, w = t >> 5;
    int i = b * 256 + t;
    int v = (i < N_NODES) ? g_deg[i] : 0;
    if (i < N_NODES) g_dinv[i] = rsqrtf((float)(v + 1));  // +1 self loop
    int x = v;
    #pragma unroll
    for (int o = 1; o < 32; o <<= 1) {
        int tv = __shfl_up_sync(0xffffffffu, x, o);
        if (lane >= o) x += tv;
    }
    if (lane == 31) wsum[w] = x;
    __syncthreads();
    if (w == 0) {
        int s = (lane < 8) ? wsum[lane] : 0;
        #pragma unroll
        for (int o = 1; o < 8; o <<= 1) {
            int tv = __shfl_up_sync(0xffffffffu, s, o);
            if (lane >= o) s += tv;
        }
        if (lane < 8) wsum[lane] = s;
    }
    __syncthreads();
    int offs = (w > 0) ? wsum[w - 1] : 0;
    int excl = x - v + offs;
    if (i < N_NODES) g_rowptr[i] = excl;
    if (t == 0) g_bsum[b] = wsum[7];
}

// scan the 196 block sums
__global__ void k_scan2() {
    __shared__ int wsum[8];
    int t = threadIdx.x, lane = t & 31, w = t >> 5;
    int v = (t < SCAN_BLOCKS) ? g_bsum[t] : 0;
    int x = v;
    #pragma unroll
    for (int o = 1; o < 32; o <<= 1) {
        int tv = __shfl_up_sync(0xffffffffu, x, o);
        if (lane >= o) x += tv;
    }
    if (lane == 31) wsum[w] = x;
    __syncthreads();
    if (w == 0) {
        int s = (lane < 8) ? wsum[lane] : 0;
        #pragma unroll
        for (int o = 1; o < 8; o <<= 1) {
            int tv = __shfl_up_sync(0xffffffffu, s, o);
            if (lane >= o) s += tv;
        }
        if (lane < 8) wsum[lane] = s;
    }
    __syncthreads();
    int offs = (w > 0) ? wsum[w - 1] : 0;
    g_boff[t] = x - v + offs;
    if (t == 0) g_rowptr[N_NODES] = N_EDGES;
}

__global__ void k_scan3() {
    int i = blockIdx.x * blockDim.x + threadIdx.x;
    if (i < N_NODES) {
        int r = g_rowptr[i] + g_boff[i >> 8];
        g_rowptr[i] = r;
        g_cursor[i] = r;
    }
}

// batch is sorted: graph pointers via binary search (lower_bound)
__global__ void k_gptr(const int* __restrict__ batch) {
    int t = threadIdx.x;
    if (t > N_GRAPHS) return;
    int lo = 0, hi = N_NODES;
    while (lo < hi) {
        int m = (lo + hi) >> 1;
        if (batch[m] < t) lo = m + 1; else hi = m;
    }
    g_gptr[t] = lo;
}

// fill CSR columns + precomputed edge weights dinv[s]*dinv[d]
__global__ void k_fill(const int* __restrict__ ei) {
    int e = blockIdx.x * blockDim.x + threadIdx.x;
    if (e < N_EDGES) {
        int s = ei[e];
        int d = ei[N_EDGES + e];
        int p = atomicAdd(&g_cursor[d], 1);
        g_col[p] = s;
        g_wt[p] = g_dinv[s] * g_dinv[d];
    }
}

// ---- layer 1 input transform: g_bufA = x @ W1 ----
__global__ void k_in_gemm(const float* __restrict__ x, const float* __restrict__ W1) {
    __shared__ float sW[D_IN * D_HID];   // 14 KB
    __shared__ float sx[16 * D_IN];
    int tid = threadIdx.x;
    for (int i = tid; i < D_IN * D_HID; i += 256) sW[i] = W1[i];
    int n0 = blockIdx.x * 16;
    int cnt = min(16, N_NODES - n0);
    for (int i = tid; i < cnt * D_IN; i += 256) sx[i] = x[(size_t)n0 * D_IN + i];
    __syncthreads();
    for (int r = 0; r < cnt; r++) {
        float acc = 0.f;
        #pragma unroll
        for (int k = 0; k < D_IN; k++) acc += sx[r * D_IN + k] * sW[k * D_HID + tid];
        g_bufA[(size_t)(n0 + r) * D_HID + tid] = acc;
    }
}

// ---- GCN aggregation: g_bufB[n] = selu( sum + bias ); reads g_bufA ----
// 64 threads/node, float4 per thread, precomputed edge weights
__global__ void k_aggregate(const float* __restrict__ bias) {
    int n = blockIdx.x, tid = threadIdx.x;
    int f = tid * 4;
    float dn = g_dinv[n];
    float sw = dn * dn;
    const float4* selfp = (const float4*)&g_bufA[(size_t)n * D_HID + f];
    float4 sv = *selfp;
    float4 accA = make_float4(sv.x * sw, sv.y * sw, sv.z * sw, sv.w * sw);
    float4 accB = make_float4(0.f, 0.f, 0.f, 0.f);
    int i = g_rowptr[n], e1 = g_rowptr[n + 1];
    for (; i + 4 <= e1; i += 4) {
        int s0 = __ldg(&g_col[i]);     float w0 = __ldg(&g_wt[i]);
        int s1 = __ldg(&g_col[i + 1]); float w1 = __ldg(&g_wt[i + 1]);
        int s2 = __ldg(&g_col[i + 2]); float w2 = __ldg(&g_wt[i + 2]);
        int s3 = __ldg(&g_col[i + 3]); float w3 = __ldg(&g_wt[i + 3]);
        float4 v0 = *(const float4*)&g_bufA[(size_t)s0 * D_HID + f];
        float4 v1 = *(const float4*)&g_bufA[(size_t)s1 * D_HID + f];
        float4 v2 = *(const float4*)&g_bufA[(size_t)s2 * D_HID + f];
        float4 v3 = *(const float4*)&g_bufA[(size_t)s3 * D_HID + f];
        accA.x += v0.x * w0; accA.y += v0.y * w0; accA.z += v0.z * w0; accA.w += v0.w * w0;
        accB.x += v1.x * w1; accB.y += v1.y * w1; accB.z += v1.z * w1; accB.w += v1.w * w1;
        accA.x += v2.x * w2; accA.y += v2.y * w2; accA.z += v2.z * w2; accA.w += v2.w * w2;
        accB.x += v3.x * w3; accB.y += v3.y * w3; accB.z += v3.z * w3; accB.w += v3.w * w3;
    }
    for (; i < e1; i++) {
        int s = __ldg(&g_col[i]); float w = __ldg(&g_wt[i]);
        float4 v = *(const float4*)&g_bufA[(size_t)s * D_HID + f];
        accA.x += v.x * w; accA.y += v.y * w; accA.z += v.z * w; accA.w += v.w * w;
    }
    float4 bb = *(const float4*)&bias[f];
    float4 o;
    o.x = selu_f(accA.x + accB.x + bb.x);
    o.y = selu_f(accA.y + accB.y + bb.y);
    o.z = selu_f(accA.z + accB.z + bb.z);
    o.w = selu_f(accA.w + accB.w + bb.w);
    *(float4*)&g_bufB[(size_t)n * D_HID + f] = o;
}

// ---- g_bufA = g_bufB @ W2 : 128x128 tile, 8x8/thread, f32x2 packed FMA ----
__global__ void __launch_bounds__(256, 2) k_gemm128(const float* __restrict__ Bw) {
    __shared__ float As[2][16][132];
    __shared__ float Bs[2][16][128];
    int t = threadIdx.x;
    int bm = blockIdx.x * 128, bn = blockIdx.y * 128;
    int tx = t & 15, ty = t >> 4;
    int am = t >> 2, ak = (t & 3) * 4;     // A-tile load coords
    int bk = t >> 5, bn4 = (t & 31) * 4;   // B-tile load coords

    unsigned long long acc[8][4];
    #pragma unroll
    for (int i = 0; i < 8; i++)
        #pragma unroll
        for (int j = 0; j < 4; j++) acc[i][j] = 0ull;

    const float4 z4 = make_float4(0.f, 0.f, 0.f, 0.f);
    float4 a0, a1, b0, b1;
    // prologue: load k0=0 tile
    {
        int r0 = bm + am, r1 = bm + am + 64;
        a0 = (r0 < N_NODES) ? *(const float4*)&g_bufB[(size_t)r0 * 256 + ak] : z4;
        a1 = (r1 < N_NODES) ? *(const float4*)&g_bufB[(size_t)r1 * 256 + ak] : z4;
        b0 = *(const float4*)&Bw[(size_t)bk * 256 + bn + bn4];
        b1 = *(const float4*)&Bw[(size_t)(bk + 8) * 256 + bn + bn4];
        As[0][ak + 0][am] = a0.x; As[0][ak + 1][am] = a0.y;
        As[0][ak + 2][am] = a0.z; As[0][ak + 3][am] = a0.w;
        As[0][ak + 0][am + 64] = a1.x; As[0][ak + 1][am + 64] = a1.y;
        As[0][ak + 2][am + 64] = a1.z; As[0][ak + 3][am + 64] = a1.w;
        *(float4*)&Bs[0][bk][bn4] = b0;
        *(float4*)&Bs[0][bk + 8][bn4] = b1;
    }
    __syncthreads();

    #pragma unroll 2
    for (int k0 = 0; k0 < 256; k0 += 16) {
        int buf = (k0 >> 4) & 1;
        bool hasNext = (k0 + 16) < 256;
        if (hasNext) {
            int kn = k0 + 16;
            int r0 = bm + am, r1 = bm + am + 64;
            a0 = (r0 < N_NODES) ? *(const float4*)&g_bufB[(size_t)r0 * 256 + kn + ak] : z4;
            a1 = (r1 < N_NODES) ? *(const float4*)&g_bufB[(size_t)r1 * 256 + kn + ak] : z4;
            b0 = *(const float4*)&Bw[(size_t)(kn + bk) * 256 + bn + bn4];
            b1 = *(const float4*)&Bw[(size_t)(kn + bk + 8) * 256 + bn + bn4];
        }
        #pragma unroll
        for (int kk = 0; kk < 16; kk++) {
            float4 av0 = *(const float4*)&As[buf][kk][ty * 8];
            float4 av1 = *(const float4*)&As[buf][kk][ty * 8 + 4];
            ulonglong2 bv0 = *(const ulonglong2*)&Bs[buf][kk][tx * 8];
            ulonglong2 bv1 = *(const ulonglong2*)&Bs[buf][kk][tx * 8 + 4];
            unsigned long long bp[4] = {bv0.x, bv0.y, bv1.x, bv1.y};
            float a[8] = {av0.x, av0.y, av0.z, av0.w, av1.x, av1.y, av1.z, av1.w};
            #pragma unroll
            for (int i = 0; i < 8; i++) {
                unsigned long long ap = dup2(a[i]);
                #pragma unroll
                for (int j = 0; j < 4; j++) ffma2(acc[i][j], ap, bp[j]);
            }
        }
        if (hasNext) {
            int nb = buf ^ 1;
            As[nb][ak + 0][am] = a0.x; As[nb][ak + 1][am] = a0.y;
            As[nb][ak + 2][am] = a0.z; As[nb][ak + 3][am] = a0.w;
            As[nb][ak + 0][am + 64] = a1.x; As[nb][ak + 1][am + 64] = a1.y;
            As[nb][ak + 2][am + 64] = a1.z; As[nb][ak + 3][am + 64] = a1.w;
            *(float4*)&Bs[nb][bk][bn4] = b0;
            *(float4*)&Bs[nb][bk + 8][bn4] = b1;
            __syncthreads();
        }
    }

    #pragma unroll
    for (int i = 0; i < 8; i++) {
        int gm = bm + ty * 8 + i;
        if (gm < N_NODES) {
            float* dst = &g_bufA[(size_t)gm * 256 + bn + tx * 8];
            *(ulonglong2*)dst = make_ulonglong2(acc[i][0], acc[i][1]);
            *(ulonglong2*)(dst + 4) = make_ulonglong2(acc[i][2], acc[i][3]);
        }
    }
}

// ---- fused head: mean-pool + selu + fc1 + selu + fc2 + log_softmax ----
__global__ void k_head(const float* __restrict__ fc1w, const float* __restrict__ fc1b,
                       const float* __restrict__ fc2w, const float* __restrict__ fc2b,
                       float* __restrict__ out) {
    __shared__ float sp[D_HID];
    __shared__ float h1[128];
    __shared__ float sl[2];
    int g = blockIdx.x, tid = threadIdx.x;  // 256 threads
    int s = g_gptr[g], e = g_gptr[g + 1];
    float acc = 0.f;
    int n = s;
    for (; n + 4 <= e; n += 4) {
        float v0 = g_bufB[(size_t)(n + 0) * D_HID + tid];
        float v1 = g_bufB[(size_t)(n + 1) * D_HID + tid];
        float v2 = g_bufB[(size_t)(n + 2) * D_HID + tid];
        float v3 = g_bufB[(size_t)(n + 3) * D_HID + tid];
        acc += (v0 + v1) + (v2 + v3);
    }
    for (; n < e; n++) acc += g_bufB[(size_t)n * D_HID + tid];
    float c = fmaxf((float)(e - s), 1.f);
    sp[tid] = selu_f(acc / c);
    __syncthreads();
    if (tid < 128) {
        float a = fc1b[tid];
        #pragma unroll 8
        for (int k = 0; k < D_HID; k++) a += sp[k] * fc1w[k * 128 + tid];
        h1[tid] = selu_f(a);
    }
    __syncthreads();
    if (tid < 64) {
        int cc = tid >> 5, lane = tid & 31;
        float p = 0.f;
        for (int k = lane; k < 128; k += 32) p += h1[k] * fc2w[k * 2 + cc];
        #pragma unroll
        for (int o = 16; o; o >>= 1) p += __shfl_down_sync(0xffffffffu, p, o);
        if (lane == 0) sl[cc] = p + fc2b[cc];
    }
    __syncthreads();
    if (tid < 2) {
        float l0 = sl[0], l1 = sl[1];
        float m = fmaxf(l0, l1);
        float lse = m + logf(expf(l0 - m) + expf(l1 - m));
        out[g * 2 + tid] = sl[tid] - lse;
    }
}

extern "C" void kernel_launch(void* const* d_in, const int* in_sizes, int n_in,
                              void* d_out, int out_size) {
    const float* x     = (const float*)d_in[0];
    const int*   ei    = (const int*)d_in[1];
    const int*   batch = (const int*)d_in[2];
    const float* W1    = (const float*)d_in[3];
    const float* b1    = (const float*)d_in[4];
    const float* W2    = (const float*)d_in[5];
    const float* b2    = (const float*)d_in[6];
    const float* fc1w  = (const float*)d_in[7];
    const float* fc1b  = (const float*)d_in[8];
    const float* fc2w  = (const float*)d_in[9];
    const float* fc2b  = (const float*)d_in[10];
    float* out = (float*)d_out;

    // CSR + normalization build (redone every call)
    k_zero<<<(N_NODES + 255) / 256, 256>>>();
    k_hist_edges<<<(N_EDGES + 255) / 256, 256>>>(ei);
    k_scan1<<<SCAN_BLOCKS, 256>>>();
    k_scan2<<<1, 256>>>();
    k_scan3<<<(N_NODES + 255) / 256, 256>>>();
    k_gptr<<<1, 512>>>(batch);
    k_fill<<<(N_EDGES + 255) / 256, 256>>>(ei);

    // layer 1
    k_in_gemm<<<(N_NODES + 15) / 16, 256>>>(x, W1);
    k_aggregate<<<N_NODES, 64>>>(b1);

    // layer 2
    dim3 g2((N_NODES + 127) / 128, 2);
    k_gemm128<<<g2, 256>>>(W2);
    k_aggregate<<<N_NODES, 64>>>(b2);

    // head
    k_head<<<N_GRAPHS, 256>>>(fc1w, fc1b, fc2w, fc2b, out);
}

// round 4
// speedup vs baseline: 1.7485x; 1.1065x over previous
#include <cuda_runtime.h>
#include <math.h>

#define N_NODES 50000
#define N_EDGES 800000
#define N_GRAPHS 256
#define D_IN 14
#define D_HID 256
#define SCAN_BLOCKS 196   // ceil(50000/256)

// ---- persistent device scratch (no dynamic allocation allowed) ----
__device__ float g_bufA[N_NODES * D_HID];   // 51.2 MB
__device__ float g_bufB[N_NODES * D_HID];   // 51.2 MB
__device__ float g_aggx[N_NODES * D_IN];    // aggregated raw input
__device__ float g_dinv[N_NODES];
__device__ int   g_deg[N_NODES];
__device__ int   g_rowptr[N_NODES + 1];
__device__ int   g_cursor[N_NODES];
__device__ int   g_col[N_EDGES];
__device__ float g_wt[N_EDGES];
__device__ int   g_bsum[256];
__device__ int   g_boff[256];
__device__ int   g_gptr[N_GRAPHS + 1];

__device__ __forceinline__ float selu_f(float x) {
    const float scale = 1.0507009873554805f;
    const float alpha = 1.6732632423543772f;
    return x > 0.f ? scale * x : scale * alpha * (expf(x) - 1.f);
}

// packed fp32x2 FMA (Blackwell): d = a*b + d per 32-bit half
__device__ __forceinline__ void ffma2(unsigned long long& d,
                                      unsigned long long a,
                                      unsigned long long b) {
    asm("fma.rn.f32x2 %0, %1, %2, %0;" : "+l"(d) : "l"(a), "l"(b));
}
__device__ __forceinline__ unsigned long long dup2(float x) {
    unsigned long long r;
    asm("mov.b64 %0, {%1, %1};" : "=l"(r) : "f"(x));
    return r;
}

// ---- CSR build ----
__global__ void k_zero() {
    int i = blockIdx.x * blockDim.x + threadIdx.x;
    if (i < N_NODES) g_deg[i] = 0;
}

__global__ void k_hist_edges(const int* __restrict__ ei) {
    int e = blockIdx.x * blockDim.x + threadIdx.x;
    if (e < N_EDGES) atomicAdd(&g_deg[ei[N_EDGES + e]], 1);
}

// block-level exclusive scan of degrees; writes partial rowptr, block sums, dinv
__global__ void k_scan1() {
    __shared__ int wsum[8];
    int b = blockIdx.x, t = threadIdx.x, lane = t & 31, w = t >> 5;
    int i = b * 256 + t;
    int v = (i < N_NODES) ? g_deg[i] : 0;
    if (i < N_NODES) g_dinv[i] = rsqrtf((float)(v + 1));  // +1 self loop
    int x = v;
    #pragma unroll
    for (int o = 1; o < 32; o <<= 1) {
        int tv = __shfl_up_sync(0xffffffffu, x, o);
        if (lane >= o) x += tv;
    }
    if (lane == 31) wsum[w] = x;
    __syncthreads();
    if (w == 0) {
        int s = (lane < 8) ? wsum[lane] : 0;
        #pragma unroll
        for (int o = 1; o < 8; o <<= 1) {
            int tv = __shfl_up_sync(0xffffffffu, s, o);
            if (lane >= o) s += tv;
        }
        if (lane < 8) wsum[lane] = s;
    }
    __syncthreads();
    int offs = (w > 0) ? wsum[w - 1] : 0;
    int excl = x - v + offs;
    if (i < N_NODES) g_rowptr[i] = excl;
    if (t == 0) g_bsum[b] = wsum[7];
}

// scan the 196 block sums
__global__ void k_scan2() {
    __shared__ int wsum[8];
    int t = threadIdx.x, lane = t & 31, w = t >> 5;
    int v = (t < SCAN_BLOCKS) ? g_bsum[t] : 0;
    int x = v;
    #pragma unroll
    for (int o = 1; o < 32; o <<= 1) {
        int tv = __shfl_up_sync(0xffffffffu, x, o);
        if (lane >= o) x += tv;
    }
    if (lane == 31) wsum[w] = x;
    __syncthreads();
    if (w == 0) {
        int s = (lane < 8) ? wsum[lane] : 0;
        #pragma unroll
        for (int o = 1; o < 8; o <<= 1) {
            int tv = __shfl_up_sync(0xffffffffu, s, o);
            if (lane >= o) s += tv;
        }
        if (lane < 8) wsum[lane] = s;
    }
    __syncthreads();
    int offs = (w > 0) ? wsum[w - 1] : 0;
    g_boff[t] = x - v + offs;
    if (t == 0) g_rowptr[N_NODES] = N_EDGES;
}

__global__ void k_scan3() {
    int i = blockIdx.x * blockDim.x + threadIdx.x;
    if (i < N_NODES) {
        int r = g_rowptr[i] + g_boff[i >> 8];
        g_rowptr[i] = r;
        g_cursor[i] = r;
    }
}

// batch is sorted: graph pointers via binary search (lower_bound)
__global__ void k_gptr(const int* __restrict__ batch) {
    int t = threadIdx.x;
    if (t > N_GRAPHS) return;
    int lo = 0, hi = N_NODES;
    while (lo < hi) {
        int m = (lo + hi) >> 1;
        if (batch[m] < t) lo = m + 1; else hi = m;
    }
    g_gptr[t] = lo;
}

// fill CSR columns + precomputed edge weights dinv[s]*dinv[d]
__global__ void k_fill(const int* __restrict__ ei) {
    int e = blockIdx.x * blockDim.x + threadIdx.x;
    if (e < N_EDGES) {
        int s = ei[e];
        int d = ei[N_EDGES + e];
        int p = atomicAdd(&g_cursor[d], 1);
        g_col[p] = s;
        g_wt[p] = g_dinv[s] * g_dinv[d];
    }
}

// ---- layer-1 aggregation on RAW 14-dim input (agg commutes with W1) ----
// one warp per node; lane halves process alternating edges
__global__ void k_agg14(const float* __restrict__ x) {
    int warp = (blockIdx.x * blockDim.x + threadIdx.x) >> 5;
    int lane = threadIdx.x & 31;
    if (warp >= N_NODES) return;
    int n = warp;
    int half = lane >> 4;        // 0 or 1
    int f = lane & 15;           // feature index (14 used)
    float acc = 0.f;
    int e0 = g_rowptr[n], e1 = g_rowptr[n + 1];
    for (int i = e0 + half; i < e1; i += 2) {
        int s = __ldg(&g_col[i]);
        float w = __ldg(&g_wt[i]);
        if (f < D_IN) acc += x[(size_t)s * D_IN + f] * w;
    }
    if (half == 0 && f < D_IN) {
        float dn = g_dinv[n];
        acc += x[(size_t)n * D_IN + f] * dn * dn;   // self loop
    }
    acc += __shfl_down_sync(0xffffffffu, acc, 16);
    if (half == 0 && f < D_IN) g_aggx[(size_t)n * D_IN + f] = acc;
}

// ---- layer-1 transform: g_bufA = selu( g_aggx @ W1 + b1 ) ----
__global__ void k_lin1(const float* __restrict__ W1, const float* __restrict__ b1) {
    __shared__ float sW[D_IN * D_HID];   // 14 KB
    __shared__ float sx[16 * D_IN];
    int tid = threadIdx.x;
    for (int i = tid; i < D_IN * D_HID; i += 256) sW[i] = W1[i];
    float bb = b1[tid];
    int n0 = blockIdx.x * 16;
    int cnt = min(16, N_NODES - n0);
    for (int i = tid; i < cnt * D_IN; i += 256) sx[i] = g_aggx[(size_t)n0 * D_IN + i];
    __syncthreads();
    for (int r = 0; r < cnt; r++) {
        float acc = bb;
        #pragma unroll
        for (int k = 0; k < D_IN; k++) acc += sx[r * D_IN + k] * sW[k * D_HID + tid];
        g_bufA[(size_t)(n0 + r) * D_HID + tid] = selu_f(acc);
    }
}

// ---- g_bufB = g_bufA @ W2 : 128x128 tile, 8x8/thread, f32x2 packed FMA ----
__global__ void __launch_bounds__(256, 2) k_gemm128(const float* __restrict__ Bw) {
    __shared__ float As[2][16][132];
    __shared__ float Bs[2][16][128];
    int t = threadIdx.x;
    int bm = blockIdx.x * 128, bn = blockIdx.y * 128;
    int tx = t & 15, ty = t >> 4;
    int am = t >> 2, ak = (t & 3) * 4;     // A-tile load coords
    int bk = t >> 5, bn4 = (t & 31) * 4;   // B-tile load coords

    unsigned long long acc[8][4];
    #pragma unroll
    for (int i = 0; i < 8; i++)
        #pragma unroll
        for (int j = 0; j < 4; j++) acc[i][j] = 0ull;

    const float4 z4 = make_float4(0.f, 0.f, 0.f, 0.f);
    float4 a0, a1, b0, b1;
    {
        int r0 = bm + am, r1 = bm + am + 64;
        a0 = (r0 < N_NODES) ? *(const float4*)&g_bufA[(size_t)r0 * 256 + ak] : z4;
        a1 = (r1 < N_NODES) ? *(const float4*)&g_bufA[(size_t)r1 * 256 + ak] : z4;
        b0 = *(const float4*)&Bw[(size_t)bk * 256 + bn + bn4];
        b1 = *(const float4*)&Bw[(size_t)(bk + 8) * 256 + bn + bn4];
        As[0][ak + 0][am] = a0.x; As[0][ak + 1][am] = a0.y;
        As[0][ak + 2][am] = a0.z; As[0][ak + 3][am] = a0.w;
        As[0][ak + 0][am + 64] = a1.x; As[0][ak + 1][am + 64] = a1.y;
        As[0][ak + 2][am + 64] = a1.z; As[0][ak + 3][am + 64] = a1.w;
        *(float4*)&Bs[0][bk][bn4] = b0;
        *(float4*)&Bs[0][bk + 8][bn4] = b1;
    }
    __syncthreads();

    #pragma unroll 2
    for (int k0 = 0; k0 < 256; k0 += 16) {
        int buf = (k0 >> 4) & 1;
        bool hasNext = (k0 + 16) < 256;
        if (hasNext) {
            int kn = k0 + 16;
            int r0 = bm + am, r1 = bm + am + 64;
            a0 = (r0 < N_NODES) ? *(const float4*)&g_bufA[(size_t)r0 * 256 + kn + ak] : z4;
            a1 = (r1 < N_NODES) ? *(const float4*)&g_bufA[(size_t)r1 * 256 + kn + ak] : z4;
            b0 = *(const float4*)&Bw[(size_t)(kn + bk) * 256 + bn + bn4];
            b1 = *(const float4*)&Bw[(size_t)(kn + bk + 8) * 256 + bn + bn4];
        }
        #pragma unroll
        for (int kk = 0; kk < 16; kk++) {
            float4 av0 = *(const float4*)&As[buf][kk][ty * 8];
            float4 av1 = *(const float4*)&As[buf][kk][ty * 8 + 4];
            ulonglong2 bv0 = *(const ulonglong2*)&Bs[buf][kk][tx * 8];
            ulonglong2 bv1 = *(const ulonglong2*)&Bs[buf][kk][tx * 8 + 4];
            unsigned long long bp[4] = {bv0.x, bv0.y, bv1.x, bv1.y};
            float a[8] = {av0.x, av0.y, av0.z, av0.w, av1.x, av1.y, av1.z, av1.w};
            #pragma unroll
            for (int i = 0; i < 8; i++) {
                unsigned long long ap = dup2(a[i]);
                #pragma unroll
                for (int j = 0; j < 4; j++) ffma2(acc[i][j], ap, bp[j]);
            }
        }
        if (hasNext) {
            int nb = buf ^ 1;
            As[nb][ak + 0][am] = a0.x; As[nb][ak + 1][am] = a0.y;
            As[nb][ak + 2][am] = a0.z; As[nb][ak + 3][am] = a0.w;
            As[nb][ak + 0][am + 64] = a1.x; As[nb][ak + 1][am + 64] = a1.y;
            As[nb][ak + 2][am + 64] = a1.z; As[nb][ak + 3][am + 64] = a1.w;
            *(float4*)&Bs[nb][bk][bn4] = b0;
            *(float4*)&Bs[nb][bk + 8][bn4] = b1;
            __syncthreads();
        }
    }

    #pragma unroll
    for (int i = 0; i < 8; i++) {
        int gm = bm + ty * 8 + i;
        if (gm < N_NODES) {
            float* dst = &g_bufB[(size_t)gm * 256 + bn + tx * 8];
            *(ulonglong2*)dst = make_ulonglong2(acc[i][0], acc[i][1]);
            *(ulonglong2*)(dst + 4) = make_ulonglong2(acc[i][2], acc[i][3]);
        }
    }
}

// ---- layer-2 aggregation: g_bufA[n] = selu( agg(g_bufB) + b2 ) ----
// 64 threads/node, float4 per thread, precomputed edge weights
__global__ void k_aggregate(const float* __restrict__ bias) {
    int n = blockIdx.x, tid = threadIdx.x;
    int f = tid * 4;
    float dn = g_dinv[n];
    float sw = dn * dn;
    float4 sv = *(const float4*)&g_bufB[(size_t)n * D_HID + f];
    float4 accA = make_float4(sv.x * sw, sv.y * sw, sv.z * sw, sv.w * sw);
    float4 accB = make_float4(0.f, 0.f, 0.f, 0.f);
    int i = g_rowptr[n], e1 = g_rowptr[n + 1];
    for (; i + 4 <= e1; i += 4) {
        int s0 = __ldg(&g_col[i]);     float w0 = __ldg(&g_wt[i]);
        int s1 = __ldg(&g_col[i + 1]); float w1 = __ldg(&g_wt[i + 1]);
        int s2 = __ldg(&g_col[i + 2]); float w2 = __ldg(&g_wt[i + 2]);
        int s3 = __ldg(&g_col[i + 3]); float w3 = __ldg(&g_wt[i + 3]);
        float4 v0 = *(const float4*)&g_bufB[(size_t)s0 * D_HID + f];
        float4 v1 = *(const float4*)&g_bufB[(size_t)s1 * D_HID + f];
        float4 v2 = *(const float4*)&g_bufB[(size_t)s2 * D_HID + f];
        float4 v3 = *(const float4*)&g_bufB[(size_t)s3 * D_HID + f];
        accA.x += v0.x * w0; accA.y += v0.y * w0; accA.z += v0.z * w0; accA.w += v0.w * w0;
        accB.x += v1.x * w1; accB.y += v1.y * w1; accB.z += v1.z * w1; accB.w += v1.w * w1;
        accA.x += v2.x * w2; accA.y += v2.y * w2; accA.z += v2.z * w2; accA.w += v2.w * w2;
        accB.x += v3.x * w3; accB.y += v3.y * w3; accB.z += v3.z * w3; accB.w += v3.w * w3;
    }
    for (; i < e1; i++) {
        int s = __ldg(&g_col[i]); float w = __ldg(&g_wt[i]);
        float4 v = *(const float4*)&g_bufB[(size_t)s * D_HID + f];
        accA.x += v.x * w; accA.y += v.y * w; accA.z += v.z * w; accA.w += v.w * w;
    }
    float4 bb = *(const float4*)&bias[f];
    float4 o;
    o.x = selu_f(accA.x + accB.x + bb.x);
    o.y = selu_f(accA.y + accB.y + bb.y);
    o.z = selu_f(accA.z + accB.z + bb.z);
    o.w = selu_f(accA.w + accB.w + bb.w);
    *(float4*)&g_bufA[(size_t)n * D_HID + f] = o;
}

// ---- fused head: mean-pool + selu + fc1 + selu + fc2 + log_softmax ----
__global__ void k_head(const float* __restrict__ fc1w, const float* __restrict__ fc1b,
                       const float* __restrict__ fc2w, const float* __restrict__ fc2b,
                       float* __restrict__ out) {
    __shared__ float sp[D_HID];
    __shared__ float h1[128];
    __shared__ float sl[2];
    int g = blockIdx.x, tid = threadIdx.x;  // 256 threads
    int s = g_gptr[g], e = g_gptr[g + 1];
    float acc = 0.f;
    int n = s;
    for (; n + 4 <= e; n += 4) {
        float v0 = g_bufA[(size_t)(n + 0) * D_HID + tid];
        float v1 = g_bufA[(size_t)(n + 1) * D_HID + tid];
        float v2 = g_bufA[(size_t)(n + 2) * D_HID + tid];
        float v3 = g_bufA[(size_t)(n + 3) * D_HID + tid];
        acc += (v0 + v1) + (v2 + v3);
    }
    for (; n < e; n++) acc += g_bufA[(size_t)n * D_HID + tid];
    float c = fmaxf((float)(e - s), 1.f);
    sp[tid] = selu_f(acc / c);
    __syncthreads();
    if (tid < 128) {
        float a = fc1b[tid];
        #pragma unroll 8
        for (int k = 0; k < D_HID; k++) a += sp[k] * fc1w[k * 128 + tid];
        h1[tid] = selu_f(a);
    }
    __syncthreads();
    if (tid < 64) {
        int cc = tid >> 5, lane = tid & 31;
        float p = 0.f;
        for (int k = lane; k < 128; k += 32) p += h1[k] * fc2w[k * 2 + cc];
        #pragma unroll
        for (int o = 16; o; o >>= 1) p += __shfl_down_sync(0xffffffffu, p, o);
        if (lane == 0) sl[cc] = p + fc2b[cc];
    }
    __syncthreads();
    if (tid < 2) {
        float l0 = sl[0], l1 = sl[1];
        float m = fmaxf(l0, l1);
        float lse = m + logf(expf(l0 - m) + expf(l1 - m));
        out[g * 2 + tid] = sl[tid] - lse;
    }
}

extern "C" void kernel_launch(void* const* d_in, const int* in_sizes, int n_in,
                              void* d_out, int out_size) {
    const float* x     = (const float*)d_in[0];
    const int*   ei    = (const int*)d_in[1];
    const int*   batch = (const int*)d_in[2];
    const float* W1    = (const float*)d_in[3];
    const float* b1    = (const float*)d_in[4];
    const float* W2    = (const float*)d_in[5];
    const float* b2    = (const float*)d_in[6];
    const float* fc1w  = (const float*)d_in[7];
    const float* fc1b  = (const float*)d_in[8];
    const float* fc2w  = (const float*)d_in[9];
    const float* fc2b  = (const float*)d_in[10];
    float* out = (float*)d_out;

    // CSR + normalization build (redone every call)
    k_zero<<<(N_NODES + 255) / 256, 256>>>();
    k_hist_edges<<<(N_EDGES + 255) / 256, 256>>>(ei);
    k_scan1<<<SCAN_BLOCKS, 256>>>();
    k_scan2<<<1, 256>>>();
    k_scan3<<<(N_NODES + 255) / 256, 256>>>();
    k_gptr<<<1, 512>>>(batch);
    k_fill<<<(N_EDGES + 255) / 256, 256>>>(ei);

    // layer 1: aggregate raw 14-dim input, then transform (+bias+selu)
    k_agg14<<<(N_NODES * 32 + 127) / 128, 128>>>(x);
    k_lin1<<<(N_NODES + 15) / 16, 256>>>(W1, b1);

    // layer 2: transform (GEMM), then aggregate (+bias+selu)
    dim3 g2((N_NODES + 127) / 128, 2);
    k_gemm128<<<g2, 256>>>(W2);
    k_aggregate<<<N_NODES, 64>>>(b2);

    // head
    k_head<<<N_GRAPHS, 256>>>(fc1w, fc1b, fc2w, fc2b, out);
}

// round 7
// speedup vs baseline: 1.9870x; 1.1364x over previous
#include <cuda_runtime.h>
#include <cuda_bf16.h>
#include <math.h>
#include <cstdint>

#define N_NODES 50000
#define N_PAD   50048            // 391 * 128
#define N_EDGES 800000
#define N_GRAPHS 256
#define D_IN 14
#define D_HID 256
#define SCAN_BLOCKS 196          // ceil(50000/256)

// ---- persistent device scratch (no dynamic allocation allowed) ----
__device__ float g_bufA[N_NODES * D_HID];                        // h2 (post-agg layer2)
__device__ float g_bufB[N_NODES * D_HID];                        // GEMM output h1@W2
__device__ __align__(16) __nv_bfloat16 g_Ah[(size_t)N_PAD * D_HID];  // h1 hi
__device__ __align__(16) __nv_bfloat16 g_Al[(size_t)N_PAD * D_HID];  // h1 lo
__device__ __align__(16) __nv_bfloat16 g_Bh[D_HID * D_HID];          // W2^T hi [n][k]
__device__ __align__(16) __nv_bfloat16 g_Bl[D_HID * D_HID];          // W2^T lo
__device__ float g_aggx[N_NODES * D_IN];
__device__ float g_dinv[N_NODES];
__device__ int   g_deg[N_NODES];
__device__ int   g_rowptr[N_NODES + 1];
__device__ int   g_cursor[N_NODES];
__device__ int   g_col[N_EDGES];
__device__ float g_wt[N_EDGES];
__device__ int   g_bsum[256];
__device__ int   g_boff[256];
__device__ int   g_gptr[N_GRAPHS + 1];

__device__ __forceinline__ float selu_f(float x) {
    const float scale = 1.0507009873554805f;
    const float alpha = 1.6732632423543772f;
    return x > 0.f ? scale * x : scale * alpha * (expf(x) - 1.f);
}

__device__ __forceinline__ uint32_t smem_u32(const void* p) {
    uint32_t a;
    asm("{ .reg .u64 t; cvta.to.shared.u64 t, %1; cvt.u32.u64 %0, t; }" : "=r"(a) : "l"(p));
    return a;
}
__device__ __forceinline__ void ldsm4(uint32_t* r, uint32_t addr) {
    asm volatile("ldmatrix.sync.aligned.m8n8.x4.shared.b16 {%0,%1,%2,%3}, [%4];"
                 : "=r"(r[0]), "=r"(r[1]), "=r"(r[2]), "=r"(r[3]) : "r"(addr));
}
__device__ __forceinline__ void mma16816(float* d, const uint32_t* a, uint32_t b0, uint32_t b1) {
    asm volatile(
        "mma.sync.aligned.m16n8k16.row.col.f32.bf16.bf16.f32 "
        "{%0,%1,%2,%3}, {%4,%5,%6,%7}, {%8,%9}, {%0,%1,%2,%3};"
        : "+f"(d[0]), "+f"(d[1]), "+f"(d[2]), "+f"(d[3])
        : "r"(a[0]), "r"(a[1]), "r"(a[2]), "r"(a[3]), "r"(b0), "r"(b1));
}

// ======================= CSR build =======================
__global__ void k_zero() {
    int i = blockIdx.x * blockDim.x + threadIdx.x;
    if (i < N_NODES) g_deg[i] = 0;
}

__global__ void k_hist_edges(const int* __restrict__ ei) {
    int e = blockIdx.x * blockDim.x + threadIdx.x;
    if (e < N_EDGES) atomicAdd(&g_deg[ei[N_EDGES + e]], 1);
}

__global__ void k_scan1() {
    __shared__ int wsum[8];
    int b = blockIdx.x, t = threadIdx.x, lane = t & 31, w = t >> 5;
    int i = b * 256 + t;
    int v = (i < N_NODES) ? g_deg[i] : 0;
    if (i < N_NODES) g_dinv[i] = rsqrtf((float)(v + 1));
    int x = v;
    #pragma unroll
    for (int o = 1; o < 32; o <<= 1) {
        int tv = __shfl_up_sync(0xffffffffu, x, o);
        if (lane >= o) x += tv;
    }
    if (lane == 31) wsum[w] = x;
    __syncthreads();
    if (w == 0) {
        int s = (lane < 8) ? wsum[lane] : 0;
        #pragma unroll
        for (int o = 1; o < 8; o <<= 1) {
            int tv = __shfl_up_sync(0xffffffffu, s, o);
            if (lane >= o) s += tv;
        }
        if (lane < 8) wsum[lane] = s;
    }
    __syncthreads();
    int offs = (w > 0) ? wsum[w - 1] : 0;
    if (i < N_NODES) g_rowptr[i] = x - v + offs;
    if (t == 0) g_bsum[b] = wsum[7];
}

__global__ void k_scan2() {
    __shared__ int wsum[8];
    int t = threadIdx.x, lane = t & 31, w = t >> 5;
    int v = (t < SCAN_BLOCKS) ? g_bsum[t] : 0;
    int x = v;
    #pragma unroll
    for (int o = 1; o < 32; o <<= 1) {
        int tv = __shfl_up_sync(0xffffffffu, x, o);
        if (lane >= o) x += tv;
    }
    if (lane == 31) wsum[w] = x;
    __syncthreads();
    if (w == 0) {
        int s = (lane < 8) ? wsum[lane] : 0;
        #pragma unroll
        for (int o = 1; o < 8; o <<= 1) {
            int tv = __shfl_up_sync(0xffffffffu, s, o);
            if (lane >= o) s += tv;
        }
        if (lane < 8) wsum[lane] = s;
    }
    __syncthreads();
    int offs = (w > 0) ? wsum[w - 1] : 0;
    g_boff[t] = x - v + offs;
    if (t == 0) g_rowptr[N_NODES] = N_EDGES;
}

__global__ void k_scan3() {
    int i = blockIdx.x * blockDim.x + threadIdx.x;
    if (i < N_NODES) {
        int r = g_rowptr[i] + g_boff[i >> 8];
        g_rowptr[i] = r;
        g_cursor[i] = r;
    }
}

__global__ void k_gptr(const int* __restrict__ batch) {
    int t = threadIdx.x;
    if (t > N_GRAPHS) return;
    int lo = 0, hi = N_NODES;
    while (lo < hi) {
        int m = (lo + hi) >> 1;
        if (batch[m] < t) lo = m + 1; else hi = m;
    }
    g_gptr[t] = lo;
}

__global__ void k_fill(const int* __restrict__ ei) {
    int e = blockIdx.x * blockDim.x + threadIdx.x;
    if (e < N_EDGES) {
        int s = ei[e];
        int d = ei[N_EDGES + e];
        int p = atomicAdd(&g_cursor[d], 1);
        g_col[p] = s;
        g_wt[p] = g_dinv[s] * g_dinv[d];
    }
}

// ---- layer-1 aggregation on RAW 14-dim input (agg commutes with W1) ----
__global__ void k_agg14(const float* __restrict__ x) {
    int warp = (blockIdx.x * blockDim.x + threadIdx.x) >> 5;
    int lane = threadIdx.x & 31;
    if (warp >= N_NODES) return;
    int n = warp;
    int half = lane >> 4;
    int f = lane & 15;
    float acc = 0.f;
    int e0 = g_rowptr[n], e1 = g_rowptr[n + 1];
    for (int i = e0 + half; i < e1; i += 2) {
        int s = __ldg(&g_col[i]);
        float w = __ldg(&g_wt[i]);
        if (f < D_IN) acc += x[(size_t)s * D_IN + f] * w;
    }
    if (half == 0 && f < D_IN) {
        float dn = g_dinv[n];
        acc += x[(size_t)n * D_IN + f] * dn * dn;
    }
    acc += __shfl_down_sync(0xffffffffu, acc, 16);
    if (half == 0 && f < D_IN) g_aggx[(size_t)n * D_IN + f] = acc;
}

// ---- layer-1 transform: h1 = selu(aggx @ W1 + b1), written as bf16 hi/lo split ----
__global__ void k_lin1(const float* __restrict__ W1, const float* __restrict__ b1) {
    __shared__ float sW[D_IN * D_HID];
    __shared__ float sx[16 * D_IN];
    int tid = threadIdx.x;
    for (int i = tid; i < D_IN * D_HID; i += 256) sW[i] = W1[i];
    float bb = b1[tid];
    int n0 = blockIdx.x * 16;
    int cnt = min(16, N_NODES - n0);
    for (int i = tid; i < cnt * D_IN; i += 256) sx[i] = g_aggx[(size_t)n0 * D_IN + i];
    __syncthreads();
    for (int r = 0; r < cnt; r++) {
        float acc = bb;
        #pragma unroll
        for (int k = 0; k < D_IN; k++) acc += sx[r * D_IN + k] * sW[k * D_HID + tid];
        float h = selu_f(acc);
        __nv_bfloat16 hh = __float2bfloat16(h);
        float rem = h - __bfloat162float(hh);
        size_t idx = (size_t)(n0 + r) * D_HID + tid;
        g_Ah[idx] = hh;
        g_Al[idx] = __float2bfloat16(rem);
    }
}

// ---- pad rows [50000, 50048): zero so MMA reads are clean ----
__global__ void k_padA() {
    int i = blockIdx.x * blockDim.x + threadIdx.x;   // 48*256
    int r = N_NODES + (i >> 8), c = i & 255;
    g_Ah[(size_t)r * D_HID + c] = __float2bfloat16(0.f);
    g_Al[(size_t)r * D_HID + c] = __float2bfloat16(0.f);
}

// ---- W2 split + transpose: g_Bh/g_Bl[n][k] = split(W2[k][n]) ----
__global__ void k_splitW2(const float* __restrict__ W2) {
    int i = blockIdx.x * blockDim.x + threadIdx.x;  // 65536
    int k = i >> 8, n = i & 255;
    float w = W2[i];
    __nv_bfloat16 wh = __float2bfloat16(w);
    float rem = w - __bfloat162float(wh);
    g_Bh[n * D_HID + k] = wh;
    g_Bl[n * D_HID + k] = __float2bfloat16(rem);
}

// ======================= split-bf16 HMMA GEMM: g_bufB = h1 @ W2 =======================
// Logical K=768: [0,256)=Ah*Bh, [256,512)=Al*Bh, [512,768)=Ah*Bl (single fp32 accum chain)
__global__ void __launch_bounds__(256, 2) k_mma() {
    __shared__ __nv_bfloat16 sA[128][40];   // stride 80B: ldmatrix conflict-free
    __shared__ __nv_bfloat16 sB[128][40];
    int tid = threadIdx.x;
    int lane = tid & 31, wid = tid >> 5;
    int warp_m = wid >> 2, warp_n = wid & 3;    // 2 x 4 warps, warp tile 64x32
    int bm = blockIdx.x * 128;
    int bn = blockIdx.y * 128;

    float acc[4][4][4];
    #pragma unroll
    for (int i = 0; i < 4; i++)
        #pragma unroll
        for (int j = 0; j < 4; j++)
            #pragma unroll
            for (int k = 0; k < 4; k++) acc[i][j][k] = 0.f;

    int lrow = tid >> 1;            // 0..127
    int lc4  = (tid & 1) * 2;       // uint4 index within 32-elem row chunk

    uint32_t aBase = smem_u32(&sA[0][0]);
    uint32_t bBase = smem_u32(&sB[0][0]);
    int tmat = lane >> 3, trow = lane & 7;

    for (int ch = 0; ch < 24; ch++) {
        int kg = ch * 32;
        const __nv_bfloat16* Asrc;
        const __nv_bfloat16* Bsrc;
        if (kg < 256)      { Asrc = g_Ah + kg;         Bsrc = g_Bh + kg; }
        else if (kg < 512) { Asrc = g_Al + (kg - 256); Bsrc = g_Bh + (kg - 256); }
        else               { Asrc = g_Ah + (kg - 512); Bsrc = g_Bl + (kg - 512); }
        __syncthreads();
        {
            const uint4* ap = (const uint4*)(Asrc + (size_t)(bm + lrow) * D_HID);
            const uint4* bp = (const uint4*)(Bsrc + (size_t)(bn + lrow) * D_HID);
            *(uint4*)&sA[lrow][lc4 * 8]       = ap[lc4];
            *(uint4*)&sA[lrow][(lc4 + 1) * 8] = ap[lc4 + 1];
            *(uint4*)&sB[lrow][lc4 * 8]       = bp[lc4];
            *(uint4*)&sB[lrow][(lc4 + 1) * 8] = bp[lc4 + 1];
        }
        __syncthreads();
        #pragma unroll
        for (int ks = 0; ks < 2; ks++) {
            uint32_t a[4][4], b[2][4];
            #pragma unroll
            for (int mt = 0; mt < 4; mt++) {
                int row = warp_m * 64 + mt * 16 + trow + (tmat & 1) * 8;
                int col = ks * 16 + (tmat >> 1) * 8;
                ldsm4(a[mt], aBase + (row * 40 + col) * 2);
            }
            #pragma unroll
            for (int np = 0; np < 2; np++) {
                int row = warp_n * 32 + np * 16 + trow + (tmat >> 1) * 8;
                int col = ks * 16 + (tmat & 1) * 8;
                ldsm4(b[np], bBase + (row * 40 + col) * 2);
            }
            #pragma unroll
            for (int mt = 0; mt < 4; mt++)
                #pragma unroll
                for (int nt = 0; nt < 4; nt++)
                    mma16816(acc[mt][nt], a[mt],
                             b[nt >> 1][(nt & 1) * 2], b[nt >> 1][(nt & 1) * 2 + 1]);
        }
    }

    // epilogue: direct float2 stores
    int gid = lane >> 2, tig = lane & 3;
    #pragma unroll
    for (int mt = 0; mt < 4; mt++) {
        #pragma unroll
        for (int nt = 0; nt < 4; nt++) {
            int r0 = bm + warp_m * 64 + mt * 16 + gid;
            int c  = bn + warp_n * 32 + nt * 8 + tig * 2;
            if (r0 < N_NODES)
                *(float2*)&g_bufB[(size_t)r0 * D_HID + c] =
                    make_float2(acc[mt][nt][0], acc[mt][nt][1]);
            int r1 = r0 + 8;
            if (r1 < N_NODES)
                *(float2*)&g_bufB[(size_t)r1 * D_HID + c] =
                    make_float2(acc[mt][nt][2], acc[mt][nt][3]);
        }
    }
}

// ---- layer-2 aggregation: g_bufA[n] = selu( agg(g_bufB) + b2 ) ----
__global__ void k_aggregate(const float* __restrict__ bias) {
    int n = blockIdx.x, tid = threadIdx.x;
    int f = tid * 4;
    float dn = g_dinv[n];
    float sw = dn * dn;
    float4 sv = *(const float4*)&g_bufB[(size_t)n * D_HID + f];
    float4 accA = make_float4(sv.x * sw, sv.y * sw, sv.z * sw, sv.w * sw);
    float4 accB = make_float4(0.f, 0.f, 0.f, 0.f);
    int i = g_rowptr[n], e1 = g_rowptr[n + 1];
    for (; i + 4 <= e1; i += 4) {
        int s0 = __ldg(&g_col[i]);     float w0 = __ldg(&g_wt[i]);
        int s1 = __ldg(&g_col[i + 1]); float w1 = __ldg(&g_wt[i + 1]);
        int s2 = __ldg(&g_col[i + 2]); float w2 = __ldg(&g_wt[i + 2]);
        int s3 = __ldg(&g_col[i + 3]); float w3 = __ldg(&g_wt[i + 3]);
        float4 v0 = *(const float4*)&g_bufB[(size_t)s0 * D_HID + f];
        float4 v1 = *(const float4*)&g_bufB[(size_t)s1 * D_HID + f];
        float4 v2 = *(const float4*)&g_bufB[(size_t)s2 * D_HID + f];
        float4 v3 = *(const float4*)&g_bufB[(size_t)s3 * D_HID + f];
        accA.x += v0.x * w0; accA.y += v0.y * w0; accA.z += v0.z * w0; accA.w += v0.w * w0;
        accB.x += v1.x * w1; accB.y += v1.y * w1; accB.z += v1.z * w1; accB.w += v1.w * w1;
        accA.x += v2.x * w2; accA.y += v2.y * w2; accA.z += v2.z * w2; accA.w += v2.w * w2;
        accB.x += v3.x * w3; accB.y += v3.y * w3; accB.z += v3.z * w3; accB.w += v3.w * w3;
    }
    for (; i < e1; i++) {
        int s = __ldg(&g_col[i]); float w = __ldg(&g_wt[i]);
        float4 v = *(const float4*)&g_bufB[(size_t)s * D_HID + f];
        accA.x += v.x * w; accA.y += v.y * w; accA.z += v.z * w; accA.w += v.w * w;
    }
    float4 bb = *(const float4*)&bias[f];
    float4 o;
    o.x = selu_f(accA.x + accB.x + bb.x);
    o.y = selu_f(accA.y + accB.y + bb.y);
    o.z = selu_f(accA.z + accB.z + bb.z);
    o.w = selu_f(accA.w + accB.w + bb.w);
    *(float4*)&g_bufA[(size_t)n * D_HID + f] = o;
}

// ---- fused head ----
__global__ void k_head(const float* __restrict__ fc1w, const float* __restrict__ fc1b,
                       const float* __restrict__ fc2w, const float* __restrict__ fc2b,
                       float* __restrict__ out) {
    __shared__ float sp[D_HID];
    __shared__ float h1[128];
    __shared__ float sl[2];
    int g = blockIdx.x, tid = threadIdx.x;
    int s = g_gptr[g], e = g_gptr[g + 1];
    float acc = 0.f;
    int n = s;
    for (; n + 4 <= e; n += 4) {
        float v0 = g_bufA[(size_t)(n + 0) * D_HID + tid];
        float v1 = g_bufA[(size_t)(n + 1) * D_HID + tid];
        float v2 = g_bufA[(size_t)(n + 2) * D_HID + tid];
        float v3 = g_bufA[(size_t)(n + 3) * D_HID + tid];
        acc += (v0 + v1) + (v2 + v3);
    }
    for (; n < e; n++) acc += g_bufA[(size_t)n * D_HID + tid];
    float c = fmaxf((float)(e - s), 1.f);
    sp[tid] = selu_f(acc / c);
    __syncthreads();
    if (tid < 128) {
        float a = fc1b[tid];
        #pragma unroll 8
        for (int k = 0; k < D_HID; k++) a += sp[k] * fc1w[k * 128 + tid];
        h1[tid] = selu_f(a);
    }
    __syncthreads();
    if (tid < 64) {
        int cc = tid >> 5, lane = tid & 31;
        float p = 0.f;
        for (int k = lane; k < 128; k += 32) p += h1[k] * fc2w[k * 2 + cc];
        #pragma unroll
        for (int o = 16; o; o >>= 1) p += __shfl_down_sync(0xffffffffu, p, o);
        if (lane == 0) sl[cc] = p + fc2b[cc];
    }
    __syncthreads();
    if (tid < 2) {
        float l0 = sl[0], l1 = sl[1];
        float m = fmaxf(l0, l1);
        float lse = m + logf(expf(l0 - m) + expf(l1 - m));
        out[g * 2 + tid] = sl[tid] - lse;
    }
}

extern "C" void kernel_launch(void* const* d_in, const int* in_sizes, int n_in,
                              void* d_out, int out_size) {
    const float* x     = (const float*)d_in[0];
    const int*   ei    = (const int*)d_in[1];
    const int*   batch = (const int*)d_in[2];
    const float* W1    = (const float*)d_in[3];
    const float* b1    = (const float*)d_in[4];
    const float* W2    = (const float*)d_in[5];
    const float* b2    = (const float*)d_in[6];
    const float* fc1w  = (const float*)d_in[7];
    const float* fc1b  = (const float*)d_in[8];
    const float* fc2w  = (const float*)d_in[9];
    const float* fc2b  = (const float*)d_in[10];
    float* out = (float*)d_out;

    // CSR + normalization build
    k_zero<<<(N_NODES + 255) / 256, 256>>>();
    k_hist_edges<<<(N_EDGES + 255) / 256, 256>>>(ei);
    k_scan1<<<SCAN_BLOCKS, 256>>>();
    k_scan2<<<1, 256>>>();
    k_scan3<<<(N_NODES + 255) / 256, 256>>>();
    k_gptr<<<1, 512>>>(batch);
    k_fill<<<(N_EDGES + 255) / 256, 256>>>(ei);

    // layer 1: aggregate raw input, transform + bf16 hi/lo split
    k_agg14<<<(N_NODES * 32 + 127) / 128, 128>>>(x);
    k_lin1<<<(N_NODES + 15) / 16, 256>>>(W1, b1);
    k_padA<<<48, 256>>>();
    k_splitW2<<<256, 256>>>(W2);

    // layer 2: HMMA split-bf16 GEMM, then aggregate (+bias+selu)
    dim3 gmma(N_PAD / 128, 2);
    k_mma<<<gmma, 256>>>();
    k_aggregate<<<N_NODES, 64>>>(b2);

    // head
    k_head<<<N_GRAPHS, 256>>>(fc1w, fc1b, fc2w, fc2b, out);
}

// round 8
// speedup vs baseline: 2.0563x; 1.0349x over previous
#include <cuda_runtime.h>
#include <cuda_bf16.h>
#include <math.h>
#include <cstdint>

#define N_NODES 50000
#define N_PAD   50048            // 391 * 128
#define N_EDGES 800000
#define N_GRAPHS 256
#define D_IN 14
#define D_HID 256
#define SCAN_BLOCKS 196          // ceil(50000/256)

// ---- persistent device scratch (no dynamic allocation allowed) ----
__device__ float g_bufA[N_NODES * D_HID];                        // h2 (post-agg layer2)
__device__ float g_bufB[N_NODES * D_HID];                        // GEMM output h1@W2
__device__ __align__(16) __nv_bfloat16 g_Ah[(size_t)N_PAD * D_HID];  // h1 hi
__device__ __align__(16) __nv_bfloat16 g_Al[(size_t)N_PAD * D_HID];  // h1 lo
__device__ __align__(16) __nv_bfloat16 g_Bh[D_HID * D_HID];          // W2^T hi [n][k]
__device__ __align__(16) __nv_bfloat16 g_Bl[D_HID * D_HID];          // W2^T lo
__device__ float g_aggx[N_NODES * D_IN];
__device__ float g_dinv[N_NODES];
__device__ int   g_deg[N_NODES];
__device__ int   g_rowptr[N_NODES + 1];
__device__ int   g_cursor[N_NODES];
__device__ int   g_col[N_EDGES];
__device__ float g_wt[N_EDGES];
__device__ int   g_bsum[256];
__device__ int   g_boff[256];
__device__ int   g_gptr[N_GRAPHS + 1];

__device__ __forceinline__ float selu_f(float x) {
    const float scale = 1.0507009873554805f;
    const float alpha = 1.6732632423543772f;
    return x > 0.f ? scale * x : scale * alpha * (expf(x) - 1.f);
}

__device__ __forceinline__ uint32_t smem_u32(const void* p) {
    uint32_t a;
    asm("{ .reg .u64 t; cvta.to.shared.u64 t, %1; cvt.u32.u64 %0, t; }" : "=r"(a) : "l"(p));
    return a;
}
__device__ __forceinline__ void ldsm4(uint32_t* r, uint32_t addr) {
    asm volatile("ldmatrix.sync.aligned.m8n8.x4.shared.b16 {%0,%1,%2,%3}, [%4];"
                 : "=r"(r[0]), "=r"(r[1]), "=r"(r[2]), "=r"(r[3]) : "r"(addr));
}
__device__ __forceinline__ void mma16816(float* d, const uint32_t* a, uint32_t b0, uint32_t b1) {
    asm volatile(
        "mma.sync.aligned.m16n8k16.row.col.f32.bf16.bf16.f32 "
        "{%0,%1,%2,%3}, {%4,%5,%6,%7}, {%8,%9}, {%0,%1,%2,%3};"
        : "+f"(d[0]), "+f"(d[1]), "+f"(d[2]), "+f"(d[3])
        : "r"(a[0]), "r"(a[1]), "r"(a[2]), "r"(a[3]), "r"(b0), "r"(b1));
}
__device__ __forceinline__ void cp16(uint32_t dst, const void* src) {
    asm volatile("cp.async.cg.shared.global [%0], [%1], 16;" :: "r"(dst), "l"(src));
}
__device__ __forceinline__ void cp_commit() {
    asm volatile("cp.async.commit_group;" ::: "memory");
}
template <int N> __device__ __forceinline__ void cp_wait() {
    asm volatile("cp.async.wait_group %0;" :: "n"(N) : "memory");
}

// ======================= CSR build =======================
__global__ void k_zero() {
    int i = blockIdx.x * blockDim.x + threadIdx.x;
    if (i < N_NODES) g_deg[i] = 0;
}

__global__ void k_hist_edges(const int* __restrict__ ei) {
    int e = blockIdx.x * blockDim.x + threadIdx.x;
    if (e < N_EDGES) atomicAdd(&g_deg[ei[N_EDGES + e]], 1);
}

__global__ void k_scan1() {
    __shared__ int wsum[8];
    int b = blockIdx.x, t = threadIdx.x, lane = t & 31, w = t >> 5;
    int i = b * 256 + t;
    int v = (i < N_NODES) ? g_deg[i] : 0;
    if (i < N_NODES) g_dinv[i] = rsqrtf((float)(v + 1));
    int x = v;
    #pragma unroll
    for (int o = 1; o < 32; o <<= 1) {
        int tv = __shfl_up_sync(0xffffffffu, x, o);
        if (lane >= o) x += tv;
    }
    if (lane == 31) wsum[w] = x;
    __syncthreads();
    if (w == 0) {
        int s = (lane < 8) ? wsum[lane] : 0;
        #pragma unroll
        for (int o = 1; o < 8; o <<= 1) {
            int tv = __shfl_up_sync(0xffffffffu, s, o);
            if (lane >= o) s += tv;
        }
        if (lane < 8) wsum[lane] = s;
    }
    __syncthreads();
    int offs = (w > 0) ? wsum[w - 1] : 0;
    if (i < N_NODES) g_rowptr[i] = x - v + offs;
    if (t == 0) g_bsum[b] = wsum[7];
}

// scan of block sums + graph-pointer binary search (fused, one block)
__global__ void k_scan2(const int* __restrict__ batch) {
    __shared__ int wsum[8];
    int t = threadIdx.x, lane = t & 31, w = t >> 5;
    int v = (t < SCAN_BLOCKS) ? g_bsum[t] : 0;
    int x = v;
    #pragma unroll
    for (int o = 1; o < 32; o <<= 1) {
        int tv = __shfl_up_sync(0xffffffffu, x, o);
        if (lane >= o) x += tv;
    }
    if (lane == 31) wsum[w] = x;
    __syncthreads();
    if (w == 0) {
        int s = (lane < 8) ? wsum[lane] : 0;
        #pragma unroll
        for (int o = 1; o < 8; o <<= 1) {
            int tv = __shfl_up_sync(0xffffffffu, s, o);
            if (lane >= o) s += tv;
        }
        if (lane < 8) wsum[lane] = s;
    }
    __syncthreads();
    int offs = (w > 0) ? wsum[w - 1] : 0;
    g_boff[t] = x - v + offs;
    if (t == 0) g_rowptr[N_NODES] = N_EDGES;
    // graph pointers (sorted batch): lower_bound per graph id
    for (int q = t; q <= N_GRAPHS; q += 256) {
        int lo = 0, hi = N_NODES;
        while (lo < hi) {
            int m = (lo + hi) >> 1;
            if (batch[m] < q) lo = m + 1; else hi = m;
        }
        g_gptr[q] = lo;
    }
}

__global__ void k_scan3() {
    int i = blockIdx.x * blockDim.x + threadIdx.x;
    if (i < N_NODES) {
        int r = g_rowptr[i] + g_boff[i >> 8];
        g_rowptr[i] = r;
        g_cursor[i] = r;
    }
}

__global__ void k_fill(const int* __restrict__ ei) {
    int e = blockIdx.x * blockDim.x + threadIdx.x;
    if (e < N_EDGES) {
        int s = ei[e];
        int d = ei[N_EDGES + e];
        int p = atomicAdd(&g_cursor[d], 1);
        g_col[p] = s;
        g_wt[p] = g_dinv[s] * g_dinv[d];
    }
}

// ---- layer-1 aggregation on RAW 14-dim input (agg commutes with W1) ----
__global__ void k_agg14(const float* __restrict__ x) {
    int warp = (blockIdx.x * blockDim.x + threadIdx.x) >> 5;
    int lane = threadIdx.x & 31;
    if (warp >= N_NODES) return;
    int n = warp;
    int half = lane >> 4;
    int f = lane & 15;
    float acc = 0.f;
    int e0 = g_rowptr[n], e1 = g_rowptr[n + 1];
    for (int i = e0 + half; i < e1; i += 2) {
        int s = __ldg(&g_col[i]);
        float w = __ldg(&g_wt[i]);
        if (f < D_IN) acc += x[(size_t)s * D_IN + f] * w;
    }
    if (half == 0 && f < D_IN) {
        float dn = g_dinv[n];
        acc += x[(size_t)n * D_IN + f] * dn * dn;
    }
    acc += __shfl_down_sync(0xffffffffu, acc, 16);
    if (half == 0 && f < D_IN) g_aggx[(size_t)n * D_IN + f] = acc;
}

// ---- layer-1 transform: h1 = selu(aggx @ W1 + b1), written as bf16 hi/lo split ----
__global__ void k_lin1(const float* __restrict__ W1, const float* __restrict__ b1) {
    __shared__ float sW[D_IN * D_HID];
    __shared__ float sx[16 * D_IN];
    int tid = threadIdx.x;
    for (int i = tid; i < D_IN * D_HID; i += 256) sW[i] = W1[i];
    float bb = b1[tid];
    int n0 = blockIdx.x * 16;
    int cnt = min(16, N_NODES - n0);
    for (int i = tid; i < cnt * D_IN; i += 256) sx[i] = g_aggx[(size_t)n0 * D_IN + i];
    __syncthreads();
    for (int r = 0; r < cnt; r++) {
        float acc = bb;
        #pragma unroll
        for (int k = 0; k < D_IN; k++) acc += sx[r * D_IN + k] * sW[k * D_HID + tid];
        float h = selu_f(acc);
        __nv_bfloat16 hh = __float2bfloat16(h);
        float rem = h - __bfloat162float(hh);
        size_t idx = (size_t)(n0 + r) * D_HID + tid;
        g_Ah[idx] = hh;
        g_Al[idx] = __float2bfloat16(rem);
    }
}

// ---- misc: W2 split+transpose (blocks 0..255) + A-row padding (blocks 256..303) ----
__global__ void k_misc(const float* __restrict__ W2) {
    int b = blockIdx.x, t = threadIdx.x;
    if (b < 256) {
        int i = b * 256 + t;       // 65536
        int k = i >> 8, n = i & 255;
        float w = W2[i];
        __nv_bfloat16 wh = __float2bfloat16(w);
        float rem = w - __bfloat162float(wh);
        g_Bh[n * D_HID + k] = wh;
        g_Bl[n * D_HID + k] = __float2bfloat16(rem);
    } else {
        int i = (b - 256) * 256 + t;   // 48*256
        int r = N_NODES + (i >> 8), c = i & 255;
        g_Ah[(size_t)r * D_HID + c] = __float2bfloat16(0.f);
        g_Al[(size_t)r * D_HID + c] = __float2bfloat16(0.f);
    }
}

// ======================= split-bf16 HMMA GEMM (cp.async double-buffered) ==============
// Logical K=768: [0,256)=Ah*Bh, [256,512)=Al*Bh, [512,768)=Ah*Bl (single fp32 accum chain)
__global__ void __launch_bounds__(256, 2) k_mma() {
    __shared__ __align__(16) __nv_bfloat16 sA[2][128][40];   // stride 80B: conflict-free
    __shared__ __align__(16) __nv_bfloat16 sB[2][128][40];
    int tid = threadIdx.x;
    int lane = tid & 31, wid = tid >> 5;
    int warp_m = wid >> 2, warp_n = wid & 3;    // 2 x 4 warps, warp tile 64x32
    int bm = blockIdx.x * 128;
    int bn = blockIdx.y * 128;

    float acc[4][4][4];
    #pragma unroll
    for (int i = 0; i < 4; i++)
        #pragma unroll
        for (int j = 0; j < 4; j++)
            #pragma unroll
            for (int k = 0; k < 4; k++) acc[i][j][k] = 0.f;

    int lrow = tid >> 1;            // 0..127
    int lc4  = (tid & 1) * 2;       // uint4 index within 32-elem row chunk

    uint32_t aB[2] = { smem_u32(&sA[0][0][0]), smem_u32(&sA[1][0][0]) };
    uint32_t bB[2] = { smem_u32(&sB[0][0][0]), smem_u32(&sB[1][0][0]) };
    int tmat = lane >> 3, trow = lane & 7;

    auto src_of = [&](int ch, const __nv_bfloat16*& Asrc, const __nv_bfloat16*& Bsrc) {
        int kg = ch * 32;
        if (kg < 256)      { Asrc = g_Ah + kg;         Bsrc = g_Bh + kg; }
        else if (kg < 512) { Asrc = g_Al + (kg - 256); Bsrc = g_Bh + (kg - 256); }
        else               { Asrc = g_Ah + (kg - 512); Bsrc = g_Bl + (kg - 512); }
    };
    auto issue = [&](int ch, int buf) {
        const __nv_bfloat16 *Asrc, *Bsrc;
        src_of(ch, Asrc, Bsrc);
        const uint4* ap = (const uint4*)(Asrc + (size_t)(bm + lrow) * D_HID);
        const uint4* bp = (const uint4*)(Bsrc + (size_t)(bn + lrow) * D_HID);
        uint32_t ad = aB[buf] + (lrow * 40 + lc4 * 8) * 2;
        uint32_t bd = bB[buf] + (lrow * 40 + lc4 * 8) * 2;
        cp16(ad,      ap + lc4);
        cp16(ad + 16, ap + lc4 + 1);
        cp16(bd,      bp + lc4);
        cp16(bd + 16, bp + lc4 + 1);
        cp_commit();
    };

    issue(0, 0);
    for (int ch = 0; ch < 24; ch++) {
        int cur = ch & 1;
        if (ch + 1 < 24) {
            issue(ch + 1, cur ^ 1);
            cp_wait<1>();
        } else {
            cp_wait<0>();
        }
        __syncthreads();
        #pragma unroll
        for (int ks = 0; ks < 2; ks++) {
            uint32_t a[4][4], b[2][4];
            #pragma unroll
            for (int mt = 0; mt < 4; mt++) {
                int row = warp_m * 64 + mt * 16 + trow + (tmat & 1) * 8;
                int col = ks * 16 + (tmat >> 1) * 8;
                ldsm4(a[mt], aB[cur] + (row * 40 + col) * 2);
            }
            #pragma unroll
            for (int np = 0; np < 2; np++) {
                int row = warp_n * 32 + np * 16 + trow + (tmat >> 1) * 8;
                int col = ks * 16 + (tmat & 1) * 8;
                ldsm4(b[np], bB[cur] + (row * 40 + col) * 2);
            }
            #pragma unroll
            for (int mt = 0; mt < 4; mt++)
                #pragma unroll
                for (int nt = 0; nt < 4; nt++)
                    mma16816(acc[mt][nt], a[mt],
                             b[nt >> 1][(nt & 1) * 2], b[nt >> 1][(nt & 1) * 2 + 1]);
        }
        __syncthreads();
    }

    // epilogue: direct float2 stores
    int gid = lane >> 2, tig = lane & 3;
    #pragma unroll
    for (int mt = 0; mt < 4; mt++) {
        #pragma unroll
        for (int nt = 0; nt < 4; nt++) {
            int r0 = bm + warp_m * 64 + mt * 16 + gid;
            int c  = bn + warp_n * 32 + nt * 8 + tig * 2;
            if (r0 < N_NODES)
                *(float2*)&g_bufB[(size_t)r0 * D_HID + c] =
                    make_float2(acc[mt][nt][0], acc[mt][nt][1]);
            int r1 = r0 + 8;
            if (r1 < N_NODES)
                *(float2*)&g_bufB[(size_t)r1 * D_HID + c] =
                    make_float2(acc[mt][nt][2], acc[mt][nt][3]);
        }
    }
}

// ---- layer-2 aggregation: g_bufA[n] = selu( agg(g_bufB) + b2 ) ----
// 128 threads = 2 nodes x 64 threads, float4 per thread
__global__ void k_aggregate(const float* __restrict__ bias) {
    int tid = threadIdx.x;
    int n = blockIdx.x * 2 + (tid >> 6);
    int f = (tid & 63) * 4;
    if (n >= N_NODES) return;
    float dn = g_dinv[n];
    float sw = dn * dn;
    float4 sv = *(const float4*)&g_bufB[(size_t)n * D_HID + f];
    float4 accA = make_float4(sv.x * sw, sv.y * sw, sv.z * sw, sv.w * sw);
    float4 accB = make_float4(0.f, 0.f, 0.f, 0.f);
    int i = g_rowptr[n], e1 = g_rowptr[n + 1];
    for (; i + 4 <= e1; i += 4) {
        int s0 = __ldg(&g_col[i]);     float w0 = __ldg(&g_wt[i]);
        int s1 = __ldg(&g_col[i + 1]); float w1 = __ldg(&g_wt[i + 1]);
        int s2 = __ldg(&g_col[i + 2]); float w2 = __ldg(&g_wt[i + 2]);
        int s3 = __ldg(&g_col[i + 3]); float w3 = __ldg(&g_wt[i + 3]);
        float4 v0 = *(const float4*)&g_bufB[(size_t)s0 * D_HID + f];
        float4 v1 = *(const float4*)&g_bufB[(size_t)s1 * D_HID + f];
        float4 v2 = *(const float4*)&g_bufB[(size_t)s2 * D_HID + f];
        float4 v3 = *(const float4*)&g_bufB[(size_t)s3 * D_HID + f];
        accA.x += v0.x * w0; accA.y += v0.y * w0; accA.z += v0.z * w0; accA.w += v0.w * w0;
        accB.x += v1.x * w1; accB.y += v1.y * w1; accB.z += v1.z * w1; accB.w += v1.w * w1;
        accA.x += v2.x * w2; accA.y += v2.y * w2; accA.z += v2.z * w2; accA.w += v2.w * w2;
        accB.x += v3.x * w3; accB.y += v3.y * w3; accB.z += v3.z * w3; accB.w += v3.w * w3;
    }
    for (; i < e1; i++) {
        int s = __ldg(&g_col[i]); float w = __ldg(&g_wt[i]);
        float4 v = *(const float4*)&g_bufB[(size_t)s * D_HID + f];
        accA.x += v.x * w; accA.y += v.y * w; accA.z += v.z * w; accA.w += v.w * w;
    }
    const float4 bb = *(const float4*)&bias[f];
    float4 o;
    o.x = selu_f(accA.x + accB.x + bb.x);
    o.y = selu_f(accA.y + accB.y + bb.y);
    o.z = selu_f(accA.z + accB.z + bb.z);
    o.w = selu_f(accA.w + accB.w + bb.w);
    *(float4*)&g_bufA[(size_t)n * D_HID + f] = o;
}

// ---- fused head ----
__global__ void k_head(const float* __restrict__ fc1w, const float* __restrict__ fc1b,
                       const float* __restrict__ fc2w, const float* __restrict__ fc2b,
                       float* __restrict__ out) {
    __shared__ float sp[D_HID];
    __shared__ float h1[128];
    __shared__ float sl[2];
    int g = blockIdx.x, tid = threadIdx.x;
    int s = g_gptr[g], e = g_gptr[g + 1];
    float acc = 0.f;
    int n = s;
    for (; n + 4 <= e; n += 4) {
        float v0 = g_bufA[(size_t)(n + 0) * D_HID + tid];
        float v1 = g_bufA[(size_t)(n + 1) * D_HID + tid];
        float v2 = g_bufA[(size_t)(n + 2) * D_HID + tid];
        float v3 = g_bufA[(size_t)(n + 3) * D_HID + tid];
        acc += (v0 + v1) + (v2 + v3);
    }
    for (; n < e; n++) acc += g_bufA[(size_t)n * D_HID + tid];
    float c = fmaxf((float)(e - s), 1.f);
    sp[tid] = selu_f(acc / c);
    __syncthreads();
    if (tid < 128) {
        float a = fc1b[tid];
        #pragma unroll 8
        for (int k = 0; k < D_HID; k++) a += sp[k] * fc1w[k * 128 + tid];
        h1[tid] = selu_f(a);
    }
    __syncthreads();
    if (tid < 64) {
        int cc = tid >> 5, lane = tid & 31;
        float p = 0.f;
        for (int k = lane; k < 128; k += 32) p += h1[k] * fc2w[k * 2 + cc];
        #pragma unroll
        for (int o = 16; o; o >>= 1) p += __shfl_down_sync(0xffffffffu, p, o);
        if (lane == 0) sl[cc] = p + fc2b[cc];
    }
    __syncthreads();
    if (tid < 2) {
        float l0 = sl[0], l1 = sl[1];
        float m = fmaxf(l0, l1);
        float lse = m + logf(expf(l0 - m) + expf(l1 - m));
        out[g * 2 + tid] = sl[tid] - lse;
    }
}

extern "C" void kernel_launch(void* const* d_in, const int* in_sizes, int n_in,
                              void* d_out, int out_size) {
    const float* x     = (const float*)d_in[0];
    const int*   ei    = (const int*)d_in[1];
    const int*   batch = (const int*)d_in[2];
    const float* W1    = (const float*)d_in[3];
    const float* b1    = (const float*)d_in[4];
    const float* W2    = (const float*)d_in[5];
    const float* b2    = (const float*)d_in[6];
    const float* fc1w  = (const float*)d_in[7];
    const float* fc1b  = (const float*)d_in[8];
    const float* fc2w  = (const float*)d_in[9];
    const float* fc2b  = (const float*)d_in[10];
    float* out = (float*)d_out;

    // CSR + normalization build
    k_zero<<<(N_NODES + 255) / 256, 256>>>();
    k_hist_edges<<<(N_EDGES + 255) / 256, 256>>>(ei);
    k_scan1<<<SCAN_BLOCKS, 256>>>();
    k_scan2<<<1, 256>>>(batch);
    k_scan3<<<(N_NODES + 255) / 256, 256>>>();
    k_fill<<<(N_EDGES + 255) / 256, 256>>>(ei);

    // layer 1: aggregate raw input, transform + bf16 hi/lo split; W2 split + pad
    k_agg14<<<(N_NODES * 32 + 127) / 128, 128>>>(x);
    k_lin1<<<(N_NODES + 15) / 16, 256>>>(W1, b1);
    k_misc<<<304, 256>>>(W2);

    // layer 2: HMMA split-bf16 GEMM (cp.async pipelined), then aggregate (+bias+selu)
    dim3 gmma(N_PAD / 128, 2);
    k_mma<<<gmma, 256>>>();
    k_aggregate<<<N_NODES / 2, 128>>>(b2);

    // head
    k_head<<<N_GRAPHS, 256>>>(fc1w, fc1b, fc2w, fc2b, out);
}

// round 10
// speedup vs baseline: 2.1007x; 1.0216x over previous
#include <cuda_runtime.h>
#include <cuda_bf16.h>
#include <math.h>
#include <cstdint>

#define N_NODES 50000
#define N_PAD   50048            // 391 * 128
#define N_EDGES 800000
#define N_GRAPHS 256
#define D_IN 14
#define D_HID 256
#define SCAN_BLOCKS 196          // ceil(50000/256)

// k_mma dynamic smem: 3 stages x (sA 128x40 + sB 128x40) bf16
#define MMA_STAGE_BYTES (128 * 40 * 2)
#define MMA_SMEM_BYTES  (6 * MMA_STAGE_BYTES)   // 61440

// ---- persistent device scratch (no dynamic allocation allowed) ----
__device__ float g_bufA[N_NODES * D_HID];                        // h2 (post-agg layer2)
__device__ float g_bufB[N_NODES * D_HID];                        // GEMM output h1@W2
__device__ __align__(16) __nv_bfloat16 g_Ah[(size_t)N_PAD * D_HID];  // h1 hi
__device__ __align__(16) __nv_bfloat16 g_Al[(size_t)N_PAD * D_HID];  // h1 lo
__device__ __align__(16) __nv_bfloat16 g_Bh[D_HID * D_HID];          // W2^T hi [n][k]
__device__ __align__(16) __nv_bfloat16 g_Bl[D_HID * D_HID];          // W2^T lo
__device__ float g_aggx[N_NODES * D_IN];
__device__ float g_dinv[N_NODES];
__device__ int   g_deg[N_NODES];
__device__ int   g_rowptr[N_NODES + 1];
__device__ int   g_cursor[N_NODES];
__device__ int   g_col[N_EDGES];
__device__ float g_wt[N_EDGES];
__device__ int   g_bsum[256];
__device__ int   g_boff[256];
__device__ int   g_gptr[N_GRAPHS + 1];

__device__ __forceinline__ float selu_f(float x) {
    const float scale = 1.0507009873554805f;
    const float alpha = 1.6732632423543772f;
    return x > 0.f ? scale * x : scale * alpha * (expf(x) - 1.f);
}

__device__ __forceinline__ uint32_t smem_u32(const void* p) {
    uint32_t a;
    asm("{ .reg .u64 t; cvta.to.shared.u64 t, %1; cvt.u32.u64 %0, t; }" : "=r"(a) : "l"(p));
    return a;
}
__device__ __forceinline__ void ldsm4(uint32_t* r, uint32_t addr) {
    asm volatile("ldmatrix.sync.aligned.m8n8.x4.shared.b16 {%0,%1,%2,%3}, [%4];"
                 : "=r"(r[0]), "=r"(r[1]), "=r"(r[2]), "=r"(r[3]) : "r"(addr));
}
__device__ __forceinline__ void mma16816(float* d, const uint32_t* a, uint32_t b0, uint32_t b1) {
    asm volatile(
        "mma.sync.aligned.m16n8k16.row.col.f32.bf16.bf16.f32 "
        "{%0,%1,%2,%3}, {%4,%5,%6,%7}, {%8,%9}, {%0,%1,%2,%3};"
        : "+f"(d[0]), "+f"(d[1]), "+f"(d[2]), "+f"(d[3])
        : "r"(a[0]), "r"(a[1]), "r"(a[2]), "r"(a[3]), "r"(b0), "r"(b1));
}
__device__ __forceinline__ void cp16(uint32_t dst, const void* src) {
    asm volatile("cp.async.cg.shared.global [%0], [%1], 16;" :: "r"(dst), "l"(src));
}
__device__ __forceinline__ void cp_commit() {
    asm volatile("cp.async.commit_group;" ::: "memory");
}
template <int N> __device__ __forceinline__ void cp_wait() {
    asm volatile("cp.async.wait_group %0;" :: "n"(N) : "memory");
}

// ======================= CSR build =======================
__global__ void k_zero() {
    int i = blockIdx.x * blockDim.x + threadIdx.x;
    if (i < N_NODES) g_deg[i] = 0;
}

__global__ void k_hist_edges(const int* __restrict__ ei) {
    int e = blockIdx.x * blockDim.x + threadIdx.x;
    if (e < N_EDGES) atomicAdd(&g_deg[ei[N_EDGES + e]], 1);
}

__global__ void k_scan1() {
    __shared__ int wsum[8];
    int b = blockIdx.x, t = threadIdx.x, lane = t & 31, w = t >> 5;
    int i = b * 256 + t;
    int v = (i < N_NODES) ? g_deg[i] : 0;
    if (i < N_NODES) g_dinv[i] = rsqrtf((float)(v + 1));
    int x = v;
    #pragma unroll
    for (int o = 1; o < 32; o <<= 1) {
        int tv = __shfl_up_sync(0xffffffffu, x, o);
        if (lane >= o) x += tv;
    }
    if (lane == 31) wsum[w] = x;
    __syncthreads();
    if (w == 0) {
        int s = (lane < 8) ? wsum[lane] : 0;
        #pragma unroll
        for (int o = 1; o < 8; o <<= 1) {
            int tv = __shfl_up_sync(0xffffffffu, s, o);
            if (lane >= o) s += tv;
        }
        if (lane < 8) wsum[lane] = s;
    }
    __syncthreads();
    int offs = (w > 0) ? wsum[w - 1] : 0;
    if (i < N_NODES) g_rowptr[i] = x - v + offs;
    if (t == 0) g_bsum[b] = wsum[7];
}

__global__ void k_scan2() {
    __shared__ int wsum[8];
    int t = threadIdx.x, lane = t & 31, w = t >> 5;
    int v = (t < SCAN_BLOCKS) ? g_bsum[t] : 0;
    int x = v;
    #pragma unroll
    for (int o = 1; o < 32; o <<= 1) {
        int tv = __shfl_up_sync(0xffffffffu, x, o);
        if (lane >= o) x += tv;
    }
    if (lane == 31) wsum[w] = x;
    __syncthreads();
    if (w == 0) {
        int s = (lane < 8) ? wsum[lane] : 0;
        #pragma unroll
        for (int o = 1; o < 8; o <<= 1) {
            int tv = __shfl_up_sync(0xffffffffu, s, o);
            if (lane >= o) s += tv;
        }
        if (lane < 8) wsum[lane] = s;
    }
    __syncthreads();
    int offs = (w > 0) ? wsum[w - 1] : 0;
    g_boff[t] = x - v + offs;
    if (t == 0) g_rowptr[N_NODES] = N_EDGES;
}

// rowptr finalize + cursor init + graph-pointer boundary detection (batch is sorted)
__global__ void k_scan3(const int* __restrict__ batch) {
    int i = blockIdx.x * blockDim.x + threadIdx.x;
    if (i < N_NODES) {
        int r = g_rowptr[i] + g_boff[i >> 8];
        g_rowptr[i] = r;
        g_cursor[i] = r;
        // gptr[g] = lower_bound(batch, g): boundary detection, parallel
        int b = batch[i];
        int prev = (i == 0) ? -1 : batch[i - 1];
        for (int g = prev + 1; g <= b; g++) g_gptr[g] = i;
        if (i == N_NODES - 1)
            for (int g = b + 1; g <= N_GRAPHS; g++) g_gptr[g] = N_NODES;
    }
}

__global__ void k_fill(const int* __restrict__ ei) {
    int e = blockIdx.x * blockDim.x + threadIdx.x;
    if (e < N_EDGES) {
        int s = ei[e];
        int d = ei[N_EDGES + e];
        int p = atomicAdd(&g_cursor[d], 1);
        g_col[p] = s;
        g_wt[p] = g_dinv[s] * g_dinv[d];
    }
}

// ---- layer-1 aggregation on RAW 14-dim input (agg commutes with W1) ----
__global__ void k_agg14(const float* __restrict__ x) {
    int warp = (blockIdx.x * blockDim.x + threadIdx.x) >> 5;
    int lane = threadIdx.x & 31;
    if (warp >= N_NODES) return;
    int n = warp;
    int half = lane >> 4;
    int f = lane & 15;
    float acc = 0.f;
    int e0 = g_rowptr[n], e1 = g_rowptr[n + 1];
    for (int i = e0 + half; i < e1; i += 2) {
        int s = __ldg(&g_col[i]);
        float w = __ldg(&g_wt[i]);
        if (f < D_IN) acc += x[(size_t)s * D_IN + f] * w;
    }
    if (half == 0 && f < D_IN) {
        float dn = g_dinv[n];
        acc += x[(size_t)n * D_IN + f] * dn * dn;
    }
    acc += __shfl_down_sync(0xffffffffu, acc, 16);
    if (half == 0 && f < D_IN) g_aggx[(size_t)n * D_IN + f] = acc;
}

// ---- layer-1 transform: h1 = selu(aggx @ W1 + b1), written as bf16 hi/lo split ----
__global__ void k_lin1(const float* __restrict__ W1, const float* __restrict__ b1) {
    __shared__ float sW[D_IN * D_HID];
    __shared__ float sx[16 * D_IN];
    int tid = threadIdx.x;
    for (int i = tid; i < D_IN * D_HID; i += 256) sW[i] = W1[i];
    float bb = b1[tid];
    int n0 = blockIdx.x * 16;
    int cnt = min(16, N_NODES - n0);
    for (int i = tid; i < cnt * D_IN; i += 256) sx[i] = g_aggx[(size_t)n0 * D_IN + i];
    __syncthreads();
    for (int r = 0; r < cnt; r++) {
        float acc = bb;
        #pragma unroll
        for (int k = 0; k < D_IN; k++) acc += sx[r * D_IN + k] * sW[k * D_HID + tid];
        float h = selu_f(acc);
        __nv_bfloat16 hh = __float2bfloat16(h);
        float rem = h - __bfloat162float(hh);
        size_t idx = (size_t)(n0 + r) * D_HID + tid;
        g_Ah[idx] = hh;
        g_Al[idx] = __float2bfloat16(rem);
    }
}

// ---- misc: W2 split+transpose (blocks 0..255) + A-row padding (blocks 256..303) ----
__global__ void k_misc(const float* __restrict__ W2) {
    int b = blockIdx.x, t = threadIdx.x;
    if (b < 256) {
        int i = b * 256 + t;       // 65536
        int k = i >> 8, n = i & 255;
        float w = W2[i];
        __nv_bfloat16 wh = __float2bfloat16(w);
        float rem = w - __bfloat162float(wh);
        g_Bh[n * D_HID + k] = wh;
        g_Bl[n * D_HID + k] = __float2bfloat16(rem);
    } else {
        int i = (b - 256) * 256 + t;   // 48*256
        int r = N_NODES + (i >> 8), c = i & 255;
        g_Ah[(size_t)r * D_HID + c] = __float2bfloat16(0.f);
        g_Al[(size_t)r * D_HID + c] = __float2bfloat16(0.f);
    }
}

// ======================= split-bf16 HMMA GEMM (3-stage cp.async ring, dyn smem) =======
// Logical K=768: [0,256)=Ah*Bh, [256,512)=Al*Bh, [512,768)=Ah*Bl (single fp32 accum chain)
__global__ void __launch_bounds__(256, 2) k_mma() {
    extern __shared__ __align__(16) char dyn[];
    // layout: stage s: sA at s*STAGE, sB at 3*STAGE + s*STAGE (rows of 40 bf16 = 80 B)
    int tid = threadIdx.x;
    int lane = tid & 31, wid = tid >> 5;
    int warp_m = wid >> 2, warp_n = wid & 3;    // 2 x 4 warps, warp tile 64x32
    int bm = blockIdx.x * 128;
    int bn = blockIdx.y * 128;

    float acc[4][4][4];
    #pragma unroll
    for (int i = 0; i < 4; i++)
        #pragma unroll
        for (int j = 0; j < 4; j++)
            #pragma unroll
            for (int k = 0; k < 4; k++) acc[i][j][k] = 0.f;

    int lrow = tid >> 1;            // 0..127
    int lc4  = (tid & 1) * 2;       // uint4 index within 32-elem row chunk

    uint32_t base = smem_u32(dyn);
    uint32_t aB[3] = { base,                       base + MMA_STAGE_BYTES,
                       base + 2 * MMA_STAGE_BYTES };
    uint32_t bB[3] = { base + 3 * MMA_STAGE_BYTES, base + 4 * MMA_STAGE_BYTES,
                       base + 5 * MMA_STAGE_BYTES };
    int tmat = lane >> 3, trow = lane & 7;

    auto src_of = [&](int ch, const __nv_bfloat16*& Asrc, const __nv_bfloat16*& Bsrc) {
        int kg = ch * 32;
        if (kg < 256)      { Asrc = g_Ah + kg;         Bsrc = g_Bh + kg; }
        else if (kg < 512) { Asrc = g_Al + (kg - 256); Bsrc = g_Bh + (kg - 256); }
        else               { Asrc = g_Ah + (kg - 512); Bsrc = g_Bl + (kg - 512); }
    };
    auto issue = [&](int ch, int buf) {
        const __nv_bfloat16 *Asrc, *Bsrc;
        src_of(ch, Asrc, Bsrc);
        const uint4* ap = (const uint4*)(Asrc + (size_t)(bm + lrow) * D_HID);
        const uint4* bp = (const uint4*)(Bsrc + (size_t)(bn + lrow) * D_HID);
        uint32_t ad = aB[buf] + (lrow * 40 + lc4 * 8) * 2;
        uint32_t bd = bB[buf] + (lrow * 40 + lc4 * 8) * 2;
        cp16(ad,      ap + lc4);
        cp16(ad + 16, ap + lc4 + 1);
        cp16(bd,      bp + lc4);
        cp16(bd + 16, bp + lc4 + 1);
        cp_commit();
    };

    issue(0, 0);
    issue(1, 1);
    for (int ch = 0; ch < 24; ch++) {
        int cur = ch % 3;
        if (ch + 2 < 24) {
            issue(ch + 2, (ch + 2) % 3);
            cp_wait<2>();
        } else if (ch + 1 < 24) {
            cp_wait<1>();
        } else {
            cp_wait<0>();
        }
        __syncthreads();
        #pragma unroll
        for (int ks = 0; ks < 2; ks++) {
            uint32_t a[4][4], b[2][4];
            #pragma unroll
            for (int mt = 0; mt < 4; mt++) {
                int row = warp_m * 64 + mt * 16 + trow + (tmat & 1) * 8;
                int col = ks * 16 + (tmat >> 1) * 8;
                ldsm4(a[mt], aB[cur] + (row * 40 + col) * 2);
            }
            #pragma unroll
            for (int np = 0; np < 2; np++) {
                int row = warp_n * 32 + np * 16 + trow + (tmat >> 1) * 8;
                int col = ks * 16 + (tmat & 1) * 8;
                ldsm4(b[np], bB[cur] + (row * 40 + col) * 2);
            }
            #pragma unroll
            for (int mt = 0; mt < 4; mt++)
                #pragma unroll
                for (int nt = 0; nt < 4; nt++)
                    mma16816(acc[mt][nt], a[mt],
                             b[nt >> 1][(nt & 1) * 2], b[nt >> 1][(nt & 1) * 2 + 1]);
        }
        __syncthreads();
    }

    // epilogue: direct float2 stores
    int gid = lane >> 2, tig = lane & 3;
    #pragma unroll
    for (int mt = 0; mt < 4; mt++) {
        #pragma unroll
        for (int nt = 0; nt < 4; nt++) {
            int r0 = bm + warp_m * 64 + mt * 16 + gid;
            int c  = bn + warp_n * 32 + nt * 8 + tig * 2;
            if (r0 < N_NODES)
                *(float2*)&g_bufB[(size_t)r0 * D_HID + c] =
                    make_float2(acc[mt][nt][0], acc[mt][nt][1]);
            int r1 = r0 + 8;
            if (r1 < N_NODES)
                *(float2*)&g_bufB[(size_t)r1 * D_HID + c] =
                    make_float2(acc[mt][nt][2], acc[mt][nt][3]);
        }
    }
}

// ---- layer-2 aggregation: g_bufA[n] = selu( agg(g_bufB) + b2 ) ----
// 128 threads = 2 nodes x 64 threads, float4 per thread
__global__ void k_aggregate(const float* __restrict__ bias) {
    int tid = threadIdx.x;
    int n = blockIdx.x * 2 + (tid >> 6);
    int f = (tid & 63) * 4;
    if (n >= N_NODES) return;
    float dn = g_dinv[n];
    float sw = dn * dn;
    float4 sv = *(const float4*)&g_bufB[(size_t)n * D_HID + f];
    float4 accA = make_float4(sv.x * sw, sv.y * sw, sv.z * sw, sv.w * sw);
    float4 accB = make_float4(0.f, 0.f, 0.f, 0.f);
    int i = g_rowptr[n], e1 = g_rowptr[n + 1];
    for (; i + 4 <= e1; i += 4) {
        int s0 = __ldg(&g_col[i]);     float w0 = __ldg(&g_wt[i]);
        int s1 = __ldg(&g_col[i + 1]); float w1 = __ldg(&g_wt[i + 1]);
        int s2 = __ldg(&g_col[i + 2]); float w2 = __ldg(&g_wt[i + 2]);
        int s3 = __ldg(&g_col[i + 3]); float w3 = __ldg(&g_wt[i + 3]);
        float4 v0 = *(const float4*)&g_bufB[(size_t)s0 * D_HID + f];
        float4 v1 = *(const float4*)&g_bufB[(size_t)s1 * D_HID + f];
        float4 v2 = *(const float4*)&g_bufB[(size_t)s2 * D_HID + f];
        float4 v3 = *(const float4*)&g_bufB[(size_t)s3 * D_HID + f];
        accA.x += v0.x * w0; accA.y += v0.y * w0; accA.z += v0.z * w0; accA.w += v0.w * w0;
        accB.x += v1.x * w1; accB.y += v1.y * w1; accB.z += v1.z * w1; accB.w += v1.w * w1;
        accA.x += v2.x * w2; accA.y += v2.y * w2; accA.z += v2.z * w2; accA.w += v2.w * w2;
        accB.x += v3.x * w3; accB.y += v3.y * w3; accB.z += v3.z * w3; accB.w += v3.w * w3;
    }
    for (; i < e1; i++) {
        int s = __ldg(&g_col[i]); float w = __ldg(&g_wt[i]);
        float4 v = *(const float4*)&g_bufB[(size_t)s * D_HID + f];
        accA.x += v.x * w; accA.y += v.y * w; accA.z += v.z * w; accA.w += v.w * w;
    }
    const float4 bb = *(const float4*)&bias[f];
    float4 o;
    o.x = selu_f(accA.x + accB.x + bb.x);
    o.y = selu_f(accA.y + accB.y + bb.y);
    o.z = selu_f(accA.z + accB.z + bb.z);
    o.w = selu_f(accA.w + accB.w + bb.w);
    *(float4*)&g_bufA[(size_t)n * D_HID + f] = o;
}

// ---- fused head ----
__global__ void k_head(const float* __restrict__ fc1w, const float* __restrict__ fc1b,
                       const float* __restrict__ fc2w, const float* __restrict__ fc2b,
                       float* __restrict__ out) {
    __shared__ float sp[D_HID];
    __shared__ float h1[128];
    __shared__ float sl[2];
    int g = blockIdx.x, tid = threadIdx.x;
    int s = g_gptr[g], e = g_gptr[g + 1];
    float acc = 0.f;
    int n = s;
    for (; n + 4 <= e; n += 4) {
        float v0 = g_bufA[(size_t)(n + 0) * D_HID + tid];
        float v1 = g_bufA[(size_t)(n + 1) * D_HID + tid];
        float v2 = g_bufA[(size_t)(n + 2) * D_HID + tid];
        float v3 = g_bufA[(size_t)(n + 3) * D_HID + tid];
        acc += (v0 + v1) + (v2 + v3);
    }
    for (; n < e; n++) acc += g_bufA[(size_t)n * D_HID + tid];
    float c = fmaxf((float)(e - s), 1.f);
    sp[tid] = selu_f(acc / c);
    __syncthreads();
    if (tid < 128) {
        float a = fc1b[tid];
        #pragma unroll 8
        for (int k = 0; k < D_HID; k++) a += sp[k] * fc1w[k * 128 + tid];
        h1[tid] = selu_f(a);
    }
    __syncthreads();
    if (tid < 64) {
        int cc = tid >> 5, lane = tid & 31;
        float p = 0.f;
        for (int k = lane; k < 128; k += 32) p += h1[k] * fc2w[k * 2 + cc];
        #pragma unroll
        for (int o = 16; o; o >>= 1) p += __shfl_down_sync(0xffffffffu, p, o);
        if (lane == 0) sl[cc] = p + fc2b[cc];
    }
    __syncthreads();
    if (tid < 2) {
        float l0 = sl[0], l1 = sl[1];
        float m = fmaxf(l0, l1);
        float lse = m + logf(expf(l0 - m) + expf(l1 - m));
        out[g * 2 + tid] = sl[tid] - lse;
    }
}

extern "C" void kernel_launch(void* const* d_in, const int* in_sizes, int n_in,
                              void* d_out, int out_size) {
    const float* x     = (const float*)d_in[0];
    const int*   ei    = (const int*)d_in[1];
    const int*   batch = (const int*)d_in[2];
    const float* W1    = (const float*)d_in[3];
    const float* b1    = (const float*)d_in[4];
    const float* W2    = (const float*)d_in[5];
    const float* b2    = (const float*)d_in[6];
    const float* fc1w  = (const float*)d_in[7];
    const float* fc1b  = (const float*)d_in[8];
    const float* fc2w  = (const float*)d_in[9];
    const float* fc2b  = (const float*)d_in[10];
    float* out = (float*)d_out;

    cudaFuncSetAttribute(k_mma, cudaFuncAttributeMaxDynamicSharedMemorySize, MMA_SMEM_BYTES);

    // CSR + normalization build
    k_zero<<<(N_NODES + 255) / 256, 256>>>();
    k_hist_edges<<<(N_EDGES + 255) / 256, 256>>>(ei);
    k_scan1<<<SCAN_BLOCKS, 256>>>();
    k_scan2<<<1, 256>>>();
    k_scan3<<<(N_NODES + 255) / 256, 256>>>(batch);
    k_fill<<<(N_EDGES + 255) / 256, 256>>>(ei);

    // layer 1: aggregate raw input, transform + bf16 hi/lo split; W2 split + pad
    k_agg14<<<(N_NODES * 32 + 127) / 128, 128>>>(x);
    k_lin1<<<(N_NODES + 15) / 16, 256>>>(W1, b1);
    k_misc<<<304, 256>>>(W2);

    // layer 2: HMMA split-bf16 GEMM (3-stage cp.async, dyn smem), then aggregate
    dim3 gmma(N_PAD / 128, 2);
    k_mma<<<gmma, 256, MMA_SMEM_BYTES>>>();
    k_aggregate<<<N_NODES / 2, 128>>>(b2);

    // head
    k_head<<<N_GRAPHS, 256>>>(fc1w, fc1b, fc2w, fc2b, out);
}